// round 3
// baseline (speedup 1.0000x reference)
#include <cuda_runtime.h>

#define BB   32
#define SS   1024
#define DD   512
#define D2   1024
#define D3   1536
#define VV   49000
#define VP   49152
#define VF   50000
#define NCB  24
#define NSC  16     /* k4 S-chunks */

__device__ __align__(16) float g_decop_t[D2 * BB];
__device__ __align__(16) float g_temp_t [D3 * BB];
__device__ __align__(16) float g_dec1   [BB * D2];
__device__ __align__(16) float g_scores [BB * SS];
__device__ __align__(16) float g_attn   [BB * SS];
__device__ __align__(16) float g_ctxpart[NSC * BB * D2];
__device__ __align__(16) float g_hidden [BB * DD];
__device__            float g_pgen  [BB];
__device__            float g_scale [BB];
__device__ __align__(16) float g_lpart [2 * BB * VP];
__device__            float g_esum  [BB * NCB];

__device__ __forceinline__ float fast_tanh(float x) {
    float y;
    asm("tanh.approx.f32 %0, %1;" : "=f"(y) : "f"(x));
    return y;
}

// K0: transpose stage
__global__ void k0_stage(const float* __restrict__ h, const float* __restrict__ c,
                         const float* __restrict__ dec_output) {
    int i = blockIdx.x * 256 + threadIdx.x;
    int k = i >> 5, b = i & 31;
    float x = (k < DD) ? h[b * DD + k] : c[b * DD + (k - DD)];
    g_decop_t[i] = x;
    if (k < DD) g_temp_t[i] = dec_output[b * DD + k];
}

// K1: dec_op1 = dec_op @ W_dec^T + b_dec
__global__ void k1_dec1(const float* __restrict__ W, const float* __restrict__ bias) {
    int t = threadIdx.x;
    int b = t & 31, g = t >> 5;
    int j0 = blockIdx.x * 8;
    float acc[8];
#pragma unroll
    for (int jj = 0; jj < 8; jj++) acc[jj] = 0.f;
    int k0 = g * 128;
    for (int k = k0; k < k0 + 128; k++) {
        float x = g_decop_t[k * 32 + b];
#pragma unroll
        for (int jj = 0; jj < 8; jj++)
            acc[jj] += W[(j0 + jj) * D2 + k] * x;
    }
    __shared__ float sred[8][8][32];
#pragma unroll
    for (int jj = 0; jj < 8; jj++) sred[g][jj][b] = acc[jj];
    __syncthreads();
    int jj = t >> 5, bo = t & 31;
    float tot = bias[j0 + jj];
#pragma unroll
    for (int gg = 0; gg < 8; gg++) tot += sred[gg][jj][bo];
    g_dec1[bo * D2 + j0 + jj] = tot;
}

// K2: scores — warp per row; dec1 + w_attn cached in smem per block
__global__ void k2_scores(const float4* __restrict__ enc1,
                          const float4* __restrict__ wattn) {
    __shared__ float4 sd1[256];
    __shared__ float4 swa[256];
    int t = threadIdx.x;
    int row0 = blockIdx.x * 8;
    int b = row0 >> 10;
    sd1[t] = ((const float4*)g_dec1)[b * 256 + t];
    swa[t] = wattn[t];
    __syncthreads();
    int lane = t & 31, w = t >> 5;
    int row = row0 + w;
    float acc = 0.f;
#pragma unroll
    for (int i = 0; i < 8; i++) {
        int c = i * 32 + lane;
        float4 e  = enc1[(size_t)row * 256 + c];
        float4 dd = sd1[c];
        float4 wa = swa[c];
        acc += fast_tanh(e.x + dd.x) * wa.x;
        acc += fast_tanh(e.y + dd.y) * wa.y;
        acc += fast_tanh(e.z + dd.z) * wa.z;
        acc += fast_tanh(e.w + dd.w) * wa.w;
    }
#pragma unroll
    for (int o = 16; o; o >>= 1) acc += __shfl_down_sync(0xffffffffu, acc, o);
    if (!lane) g_scores[row] = acc;
}

// K3: masked softmax + renorm
__global__ void k3_softmax(const int* __restrict__ src, float* __restrict__ out_attn) {
    int b = blockIdx.x, t = threadIdx.x;
    __shared__ float sm[8];
    __shared__ float bc;
    float4 s = ((const float4*)g_scores)[b * 256 + t];
    float m = fmaxf(fmaxf(s.x, s.y), fmaxf(s.z, s.w));
#pragma unroll
    for (int o = 16; o; o >>= 1) m = fmaxf(m, __shfl_down_sync(0xffffffffu, m, o));
    if (!(t & 31)) sm[t >> 5] = m;
    __syncthreads();
    if (t == 0) {
        float mm = sm[0];
#pragma unroll
        for (int i = 1; i < 8; i++) mm = fmaxf(mm, sm[i]);
        bc = mm;
    }
    __syncthreads();
    float mx = bc;
    __syncthreads();
    int4 id = ((const int4*)src)[b * 256 + t];
    float4 e;
    e.x = (id.x != 0) ? __expf(s.x - mx) : 0.f;
    e.y = (id.y != 0) ? __expf(s.y - mx) : 0.f;
    e.z = (id.z != 0) ? __expf(s.z - mx) : 0.f;
    e.w = (id.w != 0) ? __expf(s.w - mx) : 0.f;
    float sum = e.x + e.y + e.z + e.w;
#pragma unroll
    for (int o = 16; o; o >>= 1) sum += __shfl_down_sync(0xffffffffu, sum, o);
    if (!(t & 31)) sm[t >> 5] = sum;
    __syncthreads();
    if (t == 0) {
        float tt = 0.f;
#pragma unroll
        for (int i = 0; i < 8; i++) tt += sm[i];
        bc = 1.f / tt;
    }
    __syncthreads();
    float inv = bc;
    float4 a = make_float4(e.x * inv, e.y * inv, e.z * inv, e.w * inv);
    ((float4*)g_attn)[b * 256 + t] = a;
    ((float4*)out_attn)[b * 256 + t] = a;
}

// K4: context partials over NSC chunks of 64
__global__ void k4_ctx(const float4* __restrict__ enc) {
    int sc = blockIdx.x, b = blockIdx.y, t = threadIdx.x;
    float4 acc = make_float4(0.f, 0.f, 0.f, 0.f);
    int s0 = sc * (SS / NSC);
    const float*  at   = g_attn + b * SS + s0;
    const float4* base = enc + (size_t)(b * SS + s0) * 256 + t;
#pragma unroll 8
    for (int s = 0; s < SS / NSC; s++) {
        float  a = at[s];
        float4 e = base[(size_t)s * 256];
        acc.x += a * e.x; acc.y += a * e.y; acc.z += a * e.z; acc.w += a * e.w;
    }
    ((float4*)g_ctxpart)[(sc * 32 + b) * 256 + t] = acc;
}

// K5: reduce + BN; write ctx; fused p_gen
__global__ void k5_bn_pgen(const float* __restrict__ bn_m, const float* __restrict__ bn_v,
                           const float* __restrict__ gam,  const float* __restrict__ bet,
                           const float* __restrict__ Wp,   const float* __restrict__ bp,
                           const float* __restrict__ hh,   const float* __restrict__ cc,
                           const float* __restrict__ dinp, float* __restrict__ out_ctx) {
    int b = blockIdx.x, t = threadIdx.x;
    float sv[4] = {0.f, 0.f, 0.f, 0.f};
#pragma unroll
    for (int sc = 0; sc < NSC; sc++) {
        float4 p = ((const float4*)g_ctxpart)[(sc * 32 + b) * 256 + t];
        sv[0] += p.x; sv[1] += p.y; sv[2] += p.z; sv[3] += p.w;
    }
    int d = 4 * t;
    float ctx[4];
    float pp = 0.f;
#pragma unroll
    for (int i = 0; i < 4; i++) {
        int dd = d + i;
        float cx = (sv[i] - bn_m[dd]) * rsqrtf(bn_v[dd] + 1e-5f) * gam[dd] + bet[dd];
        ctx[i] = cx;
        g_temp_t[(DD + dd) * 32 + b] = cx;
        float dop = (dd < DD) ? hh[b * DD + dd] : cc[b * DD + dd - DD];
        pp += Wp[dd] * cx + Wp[D2 + dd] * dop;
    }
    ((float4*)out_ctx)[b * 256 + t] = make_float4(ctx[0], ctx[1], ctx[2], ctx[3]);
    if (t < 128) {
#pragma unroll
        for (int i = 0; i < 4; i++) {
            int dd = 4 * t + i;
            pp += Wp[2048 + dd] * dinp[b * DD + dd];
        }
    }
    __shared__ float sm[8];
#pragma unroll
    for (int o = 16; o; o >>= 1) pp += __shfl_down_sync(0xffffffffu, pp, o);
    if (!(t & 31)) sm[t >> 5] = pp;
    __syncthreads();
    if (t == 0) {
        float tot = bp[0];
#pragma unroll
        for (int i = 0; i < 8; i++) tot += sm[i];
        g_pgen[b] = 1.f / (1.f + __expf(-tot));
    }
}

// K6: hidden = temp @ W_v1^T + b_v1
__global__ void k6_hidden(const float* __restrict__ W, const float* __restrict__ bias) {
    int t = threadIdx.x;
    int b = t & 31, g = t >> 5;
    int j0 = blockIdx.x * 8;
    float acc[8];
#pragma unroll
    for (int jj = 0; jj < 8; jj++) acc[jj] = 0.f;
    int k0 = g * 192;
    for (int k = k0; k < k0 + 192; k++) {
        float x = g_temp_t[k * 32 + b];
#pragma unroll
        for (int jj = 0; jj < 8; jj++)
            acc[jj] += W[(j0 + jj) * D3 + k] * x;
    }
    __shared__ float sred[8][8][32];
#pragma unroll
    for (int jj = 0; jj < 8; jj++) sred[g][jj][b] = acc[jj];
    __syncthreads();
    int jj = t >> 5, bo = t & 31;
    float tot = bias[j0 + jj];
#pragma unroll
    for (int gg = 0; gg < 8; gg++) tot += sred[gg][jj][bo];
    g_hidden[bo * DD + j0 + jj] = tot;
}

// K8a: vocab GEMM partials, split-K 2. Block 256v x 32b x 256k; thread 4v x 8b.
// Inner loop uses packed fma.rn.f32x2 (even/odd-k partial sums in one 64-bit reg).
// Epilogue: smem transpose -> coalesced STG.128 (layout [ks][b][v] preserved).
#define WSTR 20
__global__ __launch_bounds__(256) void k8a_logits(const float* __restrict__ Wv2) {
    __shared__ float Ws[256 * WSTR];
    __shared__ float Hs[32 * 16];
    int t  = threadIdx.x;
    int tv = t & 63, tb = t >> 6;
    int v0 = blockIdx.x * 256;
    int ks = blockIdx.y;
    int kbase = ks * 256;

    unsigned long long acc2[4][8];
#pragma unroll
    for (int j = 0; j < 4; j++)
#pragma unroll
        for (int bj = 0; bj < 8; bj++) acc2[j][bj] = 0ull;

    float4 wreg[4];
    float  hreg0, hreg1;
    {
        int k0 = kbase;
#pragma unroll
        for (int li = 0; li < 4; li++) {
            int flat = li * 256 + t;
            int v = flat >> 2, kq = flat & 3;
            int gv = v0 + v;
            wreg[li] = (gv < VV)
                ? *(const float4*)(Wv2 + (size_t)gv * DD + k0 + kq * 4)
                : make_float4(0.f, 0.f, 0.f, 0.f);
        }
        hreg0 = g_hidden[((t)       >> 4) * DD + k0 + ((t)       & 15)];
        hreg1 = g_hidden[((t + 256) >> 4) * DD + k0 + ((t + 256) & 15)];
    }
    {
#pragma unroll
        for (int li = 0; li < 4; li++) {
            int flat = li * 256 + t;
            int v = flat >> 2, kq = flat & 3;
            *(float4*)(Ws + v * WSTR + kq * 4) = wreg[li];
        }
        Hs[t] = hreg0;
        Hs[t + 256] = hreg1;
    }
    __syncthreads();

    for (int tile = 0; tile < 16; tile++) {
        if (tile < 15) {
            int k0 = kbase + (tile + 1) * 16;
#pragma unroll
            for (int li = 0; li < 4; li++) {
                int flat = li * 256 + t;
                int v = flat >> 2, kq = flat & 3;
                int gv = v0 + v;
                wreg[li] = (gv < VV)
                    ? *(const float4*)(Wv2 + (size_t)gv * DD + k0 + kq * 4)
                    : make_float4(0.f, 0.f, 0.f, 0.f);
            }
            hreg0 = g_hidden[((t)       >> 4) * DD + k0 + ((t)       & 15)];
            hreg1 = g_hidden[((t + 256) >> 4) * DD + k0 + ((t + 256) & 15)];
        }
#pragma unroll
        for (int kq = 0; kq < 4; kq++) {
            ulonglong2 h2[8];
#pragma unroll
            for (int bj = 0; bj < 8; bj++)
                h2[bj] = *(const ulonglong2*)(Hs + (tb * 8 + bj) * 16 + kq * 4);
#pragma unroll
            for (int j = 0; j < 4; j++) {
                ulonglong2 w2 = *(const ulonglong2*)(Ws + (tv + 64 * j) * WSTR + kq * 4);
#pragma unroll
                for (int bj = 0; bj < 8; bj++) {
                    asm("fma.rn.f32x2 %0, %1, %2, %0;"
                        : "+l"(acc2[j][bj]) : "l"(w2.x), "l"(h2[bj].x));
                    asm("fma.rn.f32x2 %0, %1, %2, %0;"
                        : "+l"(acc2[j][bj]) : "l"(w2.y), "l"(h2[bj].y));
                }
            }
        }
        if (tile < 15) {
            __syncthreads();
#pragma unroll
            for (int li = 0; li < 4; li++) {
                int flat = li * 256 + t;
                int v = flat >> 2, kq = flat & 3;
                *(float4*)(Ws + v * WSTR + kq * 4) = wreg[li];
            }
            Hs[t] = hreg0;
            Hs[t + 256] = hreg1;
            __syncthreads();
        }
    }
    // unpack packed accumulators
    float accf[4][8];
#pragma unroll
    for (int j = 0; j < 4; j++)
#pragma unroll
        for (int bj = 0; bj < 8; bj++) {
            unsigned long long a = acc2[j][bj];
            accf[j][bj] = __uint_as_float((unsigned)(a & 0xffffffffu)) +
                          __uint_as_float((unsigned)(a >> 32));
        }
    // smem-transposed coalesced epilogue: two passes of 16 b-rows each
#pragma unroll
    for (int p = 0; p < 2; p++) {
        __syncthreads();
        if ((tb >> 1) == p) {
#pragma unroll
            for (int j = 0; j < 4; j++)
#pragma unroll
                for (int bj = 0; bj < 8; bj++)
                    Ws[((tb & 1) * 8 + bj) * 256 + tv + 64 * j] = accf[j][bj];
        }
        __syncthreads();
#pragma unroll
        for (int i = 0; i < 4; i++) {
            int idx = i * 256 + t;          // 0..1023 -> 16 rows x 64 float4
            int row = idx >> 6, col = idx & 63;
            *(float4*)(g_lpart + ((size_t)(ks * 32 + p * 16 + row) * VP + v0 + col * 4)) =
                *(const float4*)(Ws + row * 256 + col * 4);
        }
    }
}

// K8b: combine split-K + bias, exp, per-(b,chunk) sums
__global__ void k8b_exp(const float* __restrict__ bv2, float* __restrict__ dout) {
    int b = blockIdx.x, cb = blockIdx.y, t = threadIdx.x;
    int base = cb * 2048;
    float sum = 0.f;
#pragma unroll
    for (int it = 0; it < 8; it++) {
        int v = base + it * 256 + t;
        if (v < VV) {
            float l = g_lpart[(size_t)b * VP + v] + g_lpart[(size_t)(32 + b) * VP + v] + bv2[v];
            float e = __expf(l);
            dout[(size_t)b * VF + v] = e;
            sum += e;
        }
    }
    __shared__ float sm[8];
#pragma unroll
    for (int o = 16; o; o >>= 1) sum += __shfl_down_sync(0xffffffffu, sum, o);
    if (!(t & 31)) sm[t >> 5] = sum;
    __syncthreads();
    if (t == 0) {
        float tot = 0.f;
#pragma unroll
        for (int i = 0; i < 8; i++) tot += sm[i];
        g_esum[b * NCB + cb] = tot;
    }
}

// K9: scale = p_gen / sum_exp
__global__ void k9_scale() {
    int b = threadIdx.x;
    if (b < 32) {
        float s = 0.f;
#pragma unroll
        for (int i = 0; i < NCB; i++) s += g_esum[b * NCB + i];
        g_scale[b] = g_pgen[b] / s;
    }
}

// K10: p_final = p_gen * softmax; OOV region -> 0
__global__ void k10_finalize(float* __restrict__ dout) {
    int i = blockIdx.x * 256 + threadIdx.x;
    int b = i / VF;
    int v = i - b * VF;
    float p = (v < VV) ? dout[i] * g_scale[b] : 0.f;
    dout[i] = p;
}

// K11: scatter-add (1-p_gen)*attn
__global__ void k11_scatter(const int* __restrict__ src, float* __restrict__ dout) {
    int b = blockIdx.x, t = threadIdx.x;
    float omp = 1.f - g_pgen[b];
#pragma unroll
    for (int it = 0; it < 4; it++) {
        int s = it * 256 + t;
        int idx = src[b * SS + s];
        float val = omp * g_attn[b * SS + s];
        atomicAdd(dout + (size_t)b * VF + idx, val);
    }
}

// K12: zero-fix — only OOV region can still be exactly 0
__global__ void k12_fix(float* __restrict__ dout) {
    int i = blockIdx.x * 256 + threadIdx.x;
    int b = i / 1000;
    int v = VV + (i - b * 1000);
    size_t j = (size_t)b * VF + v;
    if (dout[j] == 0.f) dout[j] = 1e-12f;
}

extern "C" void kernel_launch(void* const* d_in, const int* in_sizes, int n_in,
                              void* d_out, int out_size) {
    const float* dec_output = (const float*)d_in[0];
    const float* hh         = (const float*)d_in[1];
    const float* cc         = (const float*)d_in[2];
    const float* dinp       = (const float*)d_in[3];
    const float* enc        = (const float*)d_in[4];
    const float* enc1       = (const float*)d_in[5];
    const int*   src        = (const int*)  d_in[6];
    const float* W_dec      = (const float*)d_in[7];
    const float* b_dec      = (const float*)d_in[8];
    const float* w_attn     = (const float*)d_in[9];
    const float* W_v1       = (const float*)d_in[10];
    const float* b_v1       = (const float*)d_in[11];
    const float* W_v2       = (const float*)d_in[12];
    const float* b_v2       = (const float*)d_in[13];
    const float* W_p        = (const float*)d_in[14];
    const float* b_p        = (const float*)d_in[15];
    const float* gam        = (const float*)d_in[16];
    const float* bet        = (const float*)d_in[17];
    const float* bn_m       = (const float*)d_in[18];
    const float* bn_v       = (const float*)d_in[19];

    float* dout     = (float*)d_out;
    float* out_attn = dout + BB * VF;
    float* out_ctx  = out_attn + BB * SS;

    k0_stage   <<<128, 256>>>(hh, cc, dec_output);
    k1_dec1    <<<128, 256>>>(W_dec, b_dec);
    k2_scores  <<<4096, 256>>>((const float4*)enc1, (const float4*)w_attn);
    k3_softmax <<<32, 256>>>(src, out_attn);
    k4_ctx     <<<dim3(NSC, 32), 256>>>((const float4*)enc);
    k5_bn_pgen <<<32, 256>>>(bn_m, bn_v, gam, bet, W_p, b_p, hh, cc, dinp, out_ctx);
    k6_hidden  <<<64, 256>>>(W_v1, b_v1);
    k8a_logits <<<dim3(192, 2), 256>>>(W_v2);
    k8b_exp    <<<dim3(32, NCB), 256>>>(b_v2, dout);
    k9_scale   <<<1, 32>>>();
    k10_finalize<<<6250, 256>>>(dout);
    k11_scatter<<<32, 256>>>(src, dout);
    k12_fix    <<<125, 256>>>(dout);
}

// round 4
// speedup vs baseline: 1.0474x; 1.0474x over previous
#include <cuda_runtime.h>

#define BB   32
#define SS   1024
#define DD   512
#define D2   1024
#define D3   1536
#define VV   49000
#define VP   49152
#define VF   50000
#define NCB  24
#define NSC  16

__device__ __align__(16) float g_temp_t [D3 * BB];
__device__ __align__(16) float g_dec1   [BB * D2];
__device__ __align__(16) float g_scores [BB * SS];
__device__ __align__(16) float g_attn   [BB * SS];
__device__ __align__(16) float g_ctxpart[NSC * BB * D2];
__device__ __align__(16) float g_hidden [BB * DD];
__device__            float g_pgen  [BB];
__device__ __align__(16) float g_lpart [2 * BB * VP];
__device__            float g_esum  [BB * NCB];

__device__ __forceinline__ float fast_tanh(float x) {
    float y;
    asm("tanh.approx.f32 %0, %1;" : "=f"(y) : "f"(x));
    return y;
}

// K1f: fused stage + dec_op1 GEMV. Block = 8 j outputs; thread (jj,b) owns full K.
__global__ void k1f_dec1(const float* __restrict__ h, const float* __restrict__ c,
                         const float* __restrict__ dec_output,
                         const float* __restrict__ W, const float* __restrict__ bias) {
    __shared__ float sdec[32][129];
    __shared__ float sW[8][128];
    int t = threadIdx.x;
    int jj = t >> 5, b = t & 31;
    int j0 = blockIdx.x * 8;
    // fold-in: dec_output -> g_temp_t rows 0..511 (16384 elems over 128 blocks)
    if (t < 128) {
        int i = blockIdx.x * 128 + t;
        int k = i >> 5, bb = i & 31;
        g_temp_t[i] = dec_output[bb * DD + k];
    }
    float acc = 0.f;
    for (int ch = 0; ch < 8; ch++) {
        int k0 = ch * 128;
        __syncthreads();
#pragma unroll
        for (int m = 0; m < 16; m++) {
            int e = m * 256 + t;
            int bb = e >> 7, kk = e & 127;
            int kg = k0 + kk;
            sdec[bb][kk] = (kg < DD) ? h[bb * DD + kg] : c[bb * DD + kg - DD];
        }
#pragma unroll
        for (int m = 0; m < 4; m++) {
            int e = m * 256 + t;
            int jx = e >> 7, kk = e & 127;
            sW[jx][kk] = W[(j0 + jx) * D2 + k0 + kk];
        }
        __syncthreads();
#pragma unroll 8
        for (int kk = 0; kk < 128; kk++)
            acc += sW[jj][kk] * sdec[b][kk];
    }
    g_dec1[b * D2 + j0 + jj] = acc + bias[j0 + jj];
}

// K2: scores — warp per row; dec1 + w_attn cached in smem
__global__ void k2_scores(const float4* __restrict__ enc1,
                          const float4* __restrict__ wattn) {
    __shared__ float4 sd1[256];
    __shared__ float4 swa[256];
    int t = threadIdx.x;
    int row0 = blockIdx.x * 8;
    int b = row0 >> 10;
    sd1[t] = ((const float4*)g_dec1)[b * 256 + t];
    swa[t] = wattn[t];
    __syncthreads();
    int lane = t & 31, w = t >> 5;
    int row = row0 + w;
    float acc = 0.f;
#pragma unroll
    for (int i = 0; i < 8; i++) {
        int cidx = i * 32 + lane;
        float4 e  = enc1[(size_t)row * 256 + cidx];
        float4 dd = sd1[cidx];
        float4 wa = swa[cidx];
        acc += fast_tanh(e.x + dd.x) * wa.x;
        acc += fast_tanh(e.y + dd.y) * wa.y;
        acc += fast_tanh(e.z + dd.z) * wa.z;
        acc += fast_tanh(e.w + dd.w) * wa.w;
    }
#pragma unroll
    for (int o = 16; o; o >>= 1) acc += __shfl_down_sync(0xffffffffu, acc, o);
    if (!lane) g_scores[row] = acc;
}

// K4f: fused masked-softmax (redundant per block) + context partial chunk.
__global__ void k4f_ctx(const float4* __restrict__ enc, const int* __restrict__ src,
                        float* __restrict__ out_attn) {
    int sc = blockIdx.x, b = blockIdx.y, t = threadIdx.x;
    __shared__ float satt[1024];
    __shared__ float sm[8];
    __shared__ float bc;
    float4 s = ((const float4*)g_scores)[b * 256 + t];
    float m = fmaxf(fmaxf(s.x, s.y), fmaxf(s.z, s.w));
#pragma unroll
    for (int o = 16; o; o >>= 1) m = fmaxf(m, __shfl_down_sync(0xffffffffu, m, o));
    if (!(t & 31)) sm[t >> 5] = m;
    __syncthreads();
    if (t == 0) {
        float mm = sm[0];
#pragma unroll
        for (int i = 1; i < 8; i++) mm = fmaxf(mm, sm[i]);
        bc = mm;
    }
    __syncthreads();
    float mx = bc;
    __syncthreads();
    int4 id = ((const int4*)src)[b * 256 + t];
    float4 e;
    e.x = (id.x != 0) ? __expf(s.x - mx) : 0.f;
    e.y = (id.y != 0) ? __expf(s.y - mx) : 0.f;
    e.z = (id.z != 0) ? __expf(s.z - mx) : 0.f;
    e.w = (id.w != 0) ? __expf(s.w - mx) : 0.f;
    float sum = e.x + e.y + e.z + e.w;
#pragma unroll
    for (int o = 16; o; o >>= 1) sum += __shfl_down_sync(0xffffffffu, sum, o);
    if (!(t & 31)) sm[t >> 5] = sum;
    __syncthreads();
    if (t == 0) {
        float tt = 0.f;
#pragma unroll
        for (int i = 0; i < 8; i++) tt += sm[i];
        bc = 1.f / tt;
    }
    __syncthreads();
    float inv = bc;
    float4 a = make_float4(e.x * inv, e.y * inv, e.z * inv, e.w * inv);
    ((float4*)satt)[t] = a;
    __syncthreads();
    if (sc == 0) {
        ((float4*)g_attn)[b * 256 + t] = a;
        ((float4*)out_attn)[b * 256 + t] = a;
    }
    int s0 = sc * (SS / NSC);
    float4 acc = make_float4(0.f, 0.f, 0.f, 0.f);
    const float4* base = enc + (size_t)(b * SS + s0) * 256 + t;
#pragma unroll 8
    for (int ss = 0; ss < SS / NSC; ss++) {
        float  aa = satt[s0 + ss];
        float4 ee = base[(size_t)ss * 256];
        acc.x += aa * ee.x; acc.y += aa * ee.y; acc.z += aa * ee.z; acc.w += aa * ee.w;
    }
    ((float4*)g_ctxpart)[(sc * 32 + b) * 256 + t] = acc;
}

// K5: reduce + BN; write ctx; fused p_gen
__global__ void k5_bn_pgen(const float* __restrict__ bn_m, const float* __restrict__ bn_v,
                           const float* __restrict__ gam,  const float* __restrict__ bet,
                           const float* __restrict__ Wp,   const float* __restrict__ bp,
                           const float* __restrict__ hh,   const float* __restrict__ cc,
                           const float* __restrict__ dinp, float* __restrict__ out_ctx) {
    int b = blockIdx.x, t = threadIdx.x;
    float sv[4] = {0.f, 0.f, 0.f, 0.f};
#pragma unroll
    for (int sc = 0; sc < NSC; sc++) {
        float4 p = ((const float4*)g_ctxpart)[(sc * 32 + b) * 256 + t];
        sv[0] += p.x; sv[1] += p.y; sv[2] += p.z; sv[3] += p.w;
    }
    int d = 4 * t;
    float ctx[4];
    float pp = 0.f;
#pragma unroll
    for (int i = 0; i < 4; i++) {
        int dd = d + i;
        float cx = (sv[i] - bn_m[dd]) * rsqrtf(bn_v[dd] + 1e-5f) * gam[dd] + bet[dd];
        ctx[i] = cx;
        g_temp_t[(DD + dd) * 32 + b] = cx;
        float dop = (dd < DD) ? hh[b * DD + dd] : cc[b * DD + dd - DD];
        pp += Wp[dd] * cx + Wp[D2 + dd] * dop;
    }
    ((float4*)out_ctx)[b * 256 + t] = make_float4(ctx[0], ctx[1], ctx[2], ctx[3]);
    if (t < 128) {
#pragma unroll
        for (int i = 0; i < 4; i++) {
            int dd = 4 * t + i;
            pp += Wp[2048 + dd] * dinp[b * DD + dd];
        }
    }
    __shared__ float sm[8];
#pragma unroll
    for (int o = 16; o; o >>= 1) pp += __shfl_down_sync(0xffffffffu, pp, o);
    if (!(t & 31)) sm[t >> 5] = pp;
    __syncthreads();
    if (t == 0) {
        float tot = bp[0];
#pragma unroll
        for (int i = 0; i < 8; i++) tot += sm[i];
        g_pgen[b] = 1.f / (1.f + __expf(-tot));
    }
}

// K6: hidden = temp @ W_v1^T + b_v1
__global__ void k6_hidden(const float* __restrict__ W, const float* __restrict__ bias) {
    int t = threadIdx.x;
    int b = t & 31, g = t >> 5;
    int j0 = blockIdx.x * 8;
    float acc[8];
#pragma unroll
    for (int jj = 0; jj < 8; jj++) acc[jj] = 0.f;
    int k0 = g * 192;
    for (int k = k0; k < k0 + 192; k++) {
        float x = g_temp_t[k * 32 + b];
#pragma unroll
        for (int jj = 0; jj < 8; jj++)
            acc[jj] += W[(j0 + jj) * D3 + k] * x;
    }
    __shared__ float sred[8][8][32];
#pragma unroll
    for (int jj = 0; jj < 8; jj++) sred[g][jj][b] = acc[jj];
    __syncthreads();
    int jj = t >> 5, bo = t & 31;
    float tot = bias[j0 + jj];
#pragma unroll
    for (int gg = 0; gg < 8; gg++) tot += sred[gg][jj][bo];
    g_hidden[bo * DD + j0 + jj] = tot;
}

// K8a: vocab GEMM partials, split-K 2. Block 256v x 32b x 256k; thread 4v x 8b.
#define WSTR 20
__global__ __launch_bounds__(256) void k8a_logits(const float* __restrict__ Wv2) {
    __shared__ float Ws[256 * WSTR];
    __shared__ float Hs[32 * 16];
    int t  = threadIdx.x;
    int tv = t & 63, tb = t >> 6;
    int v0 = blockIdx.x * 256;
    int ks = blockIdx.y;
    int kbase = ks * 256;

    unsigned long long acc2[4][8];
#pragma unroll
    for (int j = 0; j < 4; j++)
#pragma unroll
        for (int bj = 0; bj < 8; bj++) acc2[j][bj] = 0ull;

    float4 wreg[4];
    float  hreg0, hreg1;
    {
        int k0 = kbase;
#pragma unroll
        for (int li = 0; li < 4; li++) {
            int flat = li * 256 + t;
            int v = flat >> 2, kq = flat & 3;
            int gv = v0 + v;
            wreg[li] = (gv < VV)
                ? *(const float4*)(Wv2 + (size_t)gv * DD + k0 + kq * 4)
                : make_float4(0.f, 0.f, 0.f, 0.f);
        }
        hreg0 = g_hidden[((t)       >> 4) * DD + k0 + ((t)       & 15)];
        hreg1 = g_hidden[((t + 256) >> 4) * DD + k0 + ((t + 256) & 15)];
    }
    {
#pragma unroll
        for (int li = 0; li < 4; li++) {
            int flat = li * 256 + t;
            int v = flat >> 2, kq = flat & 3;
            *(float4*)(Ws + v * WSTR + kq * 4) = wreg[li];
        }
        Hs[t] = hreg0;
        Hs[t + 256] = hreg1;
    }
    __syncthreads();

    for (int tile = 0; tile < 16; tile++) {
        if (tile < 15) {
            int k0 = kbase + (tile + 1) * 16;
#pragma unroll
            for (int li = 0; li < 4; li++) {
                int flat = li * 256 + t;
                int v = flat >> 2, kq = flat & 3;
                int gv = v0 + v;
                wreg[li] = (gv < VV)
                    ? *(const float4*)(Wv2 + (size_t)gv * DD + k0 + kq * 4)
                    : make_float4(0.f, 0.f, 0.f, 0.f);
            }
            hreg0 = g_hidden[((t)       >> 4) * DD + k0 + ((t)       & 15)];
            hreg1 = g_hidden[((t + 256) >> 4) * DD + k0 + ((t + 256) & 15)];
        }
#pragma unroll
        for (int kq = 0; kq < 4; kq++) {
            ulonglong2 h2[8];
#pragma unroll
            for (int bj = 0; bj < 8; bj++)
                h2[bj] = *(const ulonglong2*)(Hs + (tb * 8 + bj) * 16 + kq * 4);
#pragma unroll
            for (int j = 0; j < 4; j++) {
                ulonglong2 w2 = *(const ulonglong2*)(Ws + (tv + 64 * j) * WSTR + kq * 4);
#pragma unroll
                for (int bj = 0; bj < 8; bj++) {
                    asm("fma.rn.f32x2 %0, %1, %2, %0;"
                        : "+l"(acc2[j][bj]) : "l"(w2.x), "l"(h2[bj].x));
                    asm("fma.rn.f32x2 %0, %1, %2, %0;"
                        : "+l"(acc2[j][bj]) : "l"(w2.y), "l"(h2[bj].y));
                }
            }
        }
        if (tile < 15) {
            __syncthreads();
#pragma unroll
            for (int li = 0; li < 4; li++) {
                int flat = li * 256 + t;
                int v = flat >> 2, kq = flat & 3;
                *(float4*)(Ws + v * WSTR + kq * 4) = wreg[li];
            }
            Hs[t] = hreg0;
            Hs[t + 256] = hreg1;
            __syncthreads();
        }
    }
    float accf[4][8];
#pragma unroll
    for (int j = 0; j < 4; j++)
#pragma unroll
        for (int bj = 0; bj < 8; bj++) {
            unsigned long long a = acc2[j][bj];
            accf[j][bj] = __uint_as_float((unsigned)(a & 0xffffffffu)) +
                          __uint_as_float((unsigned)(a >> 32));
        }
#pragma unroll
    for (int p = 0; p < 2; p++) {
        __syncthreads();
        if ((tb >> 1) == p) {
#pragma unroll
            for (int j = 0; j < 4; j++)
#pragma unroll
                for (int bj = 0; bj < 8; bj++)
                    Ws[((tb & 1) * 8 + bj) * 256 + tv + 64 * j] = accf[j][bj];
        }
        __syncthreads();
#pragma unroll
        for (int i = 0; i < 4; i++) {
            int idx = i * 256 + t;
            int row = idx >> 6, col = idx & 63;
            *(float4*)(g_lpart + ((size_t)(ks * 32 + p * 16 + row) * VP + v0 + col * 4)) =
                *(const float4*)(Ws + row * 256 + col * 4);
        }
    }
}

// K8b: combine split-K + bias, exp, per-(b,chunk) sums
__global__ void k8b_exp(const float* __restrict__ bv2, float* __restrict__ dout) {
    int b = blockIdx.x, cb = blockIdx.y, t = threadIdx.x;
    int base = cb * 2048;
    float sum = 0.f;
#pragma unroll
    for (int it = 0; it < 8; it++) {
        int v = base + it * 256 + t;
        if (v < VV) {
            float l = g_lpart[(size_t)b * VP + v] + g_lpart[(size_t)(32 + b) * VP + v] + bv2[v];
            float e = __expf(l);
            dout[(size_t)b * VF + v] = e;
            sum += e;
        }
    }
    __shared__ float sm[8];
#pragma unroll
    for (int o = 16; o; o >>= 1) sum += __shfl_down_sync(0xffffffffu, sum, o);
    if (!(t & 31)) sm[t >> 5] = sum;
    __syncthreads();
    if (t == 0) {
        float tot = 0.f;
#pragma unroll
        for (int i = 0; i < 8; i++) tot += sm[i];
        g_esum[b * NCB + cb] = tot;
    }
}

// K10f: fused scale computation + p_final = p_gen * softmax; OOV -> 0
__global__ void k10f_finalize(float* __restrict__ dout) {
    int i0 = blockIdx.x * 256;
    int i = i0 + threadIdx.x;
    __shared__ float ssc[2];
    int bstart = i0 / VF;
    if (threadIdx.x < 2) {
        int b = bstart + (int)threadIdx.x;
        float sc = 0.f;
        if (b < BB) {
            float s = 0.f;
#pragma unroll
            for (int j = 0; j < NCB; j++) s += g_esum[b * NCB + j];
            sc = g_pgen[b] / s;
        }
        ssc[threadIdx.x] = sc;
    }
    __syncthreads();
    int b = i / VF;
    int v = i - b * VF;
    float p = (v < VV) ? dout[i] * ssc[b - bstart] : 0.f;
    dout[i] = p;
}

// K11f: scatter-add (1-p_gen)*attn, then OOV zero-fix (same block owns row b)
__global__ void k11f_scatter(const int* __restrict__ src, float* __restrict__ dout) {
    int b = blockIdx.x, t = threadIdx.x;
    float omp = 1.f - g_pgen[b];
#pragma unroll
    for (int it = 0; it < 4; it++) {
        int s = it * 256 + t;
        int idx = src[b * SS + s];
        float val = omp * g_attn[b * SS + s];
        atomicAdd(dout + (size_t)b * VF + idx, val);
    }
    __threadfence();
    __syncthreads();
    if (t < 250) {
#pragma unroll
        for (int q = 0; q < 4; q++) {
            int v = VV + t * 4 + q;
            size_t j = (size_t)b * VF + v;
            if (dout[j] == 0.f) dout[j] = 1e-12f;
        }
    }
}

extern "C" void kernel_launch(void* const* d_in, const int* in_sizes, int n_in,
                              void* d_out, int out_size) {
    const float* dec_output = (const float*)d_in[0];
    const float* hh         = (const float*)d_in[1];
    const float* cc         = (const float*)d_in[2];
    const float* dinp       = (const float*)d_in[3];
    const float* enc        = (const float*)d_in[4];
    const float* enc1       = (const float*)d_in[5];
    const int*   src        = (const int*)  d_in[6];
    const float* W_dec      = (const float*)d_in[7];
    const float* b_dec      = (const float*)d_in[8];
    const float* w_attn     = (const float*)d_in[9];
    const float* W_v1       = (const float*)d_in[10];
    const float* b_v1       = (const float*)d_in[11];
    const float* W_v2       = (const float*)d_in[12];
    const float* b_v2       = (const float*)d_in[13];
    const float* W_p        = (const float*)d_in[14];
    const float* b_p        = (const float*)d_in[15];
    const float* gam        = (const float*)d_in[16];
    const float* bet        = (const float*)d_in[17];
    const float* bn_m       = (const float*)d_in[18];
    const float* bn_v       = (const float*)d_in[19];

    float* dout     = (float*)d_out;
    float* out_attn = dout + BB * VF;
    float* out_ctx  = out_attn + BB * SS;

    k1f_dec1   <<<128, 256>>>(hh, cc, dec_output, W_dec, b_dec);
    k2_scores  <<<4096, 256>>>((const float4*)enc1, (const float4*)w_attn);
    k4f_ctx    <<<dim3(NSC, 32), 256>>>((const float4*)enc, src, out_attn);
    k5_bn_pgen <<<32, 256>>>(bn_m, bn_v, gam, bet, W_p, b_p, hh, cc, dinp, out_ctx);
    k6_hidden  <<<64, 256>>>(W_v1, b_v1);
    k8a_logits <<<dim3(192, 2), 256>>>(W_v2);
    k8b_exp    <<<dim3(32, NCB), 256>>>(b_v2, dout);
    k10f_finalize<<<6250, 256>>>(dout);
    k11f_scatter <<<32, 256>>>(src, dout);
}

// round 5
// speedup vs baseline: 1.1758x; 1.1227x over previous
#include <cuda_runtime.h>

#define BB   32
#define SS   1024
#define DD   512
#define D2   1024
#define D3   1536
#define VV   49000
#define VP   49152
#define VF   50000
#define NCB  25
#define NSC  16

__device__ __align__(16) float g_temp_t [D3 * BB];
__device__ __align__(16) float g_dec1   [BB * D2];
__device__ __align__(16) float g_scores [BB * SS];
__device__ __align__(16) float g_attn   [BB * SS];
__device__ __align__(16) float g_ctxpart[NSC * BB * D2];
__device__ __align__(16) float g_hidden [BB * DD];
__device__            float g_pgen  [BB];
__device__ __align__(16) float g_lpart [2 * BB * VP];
__device__            float g_sumtot[BB];
__device__            int   g_ctr_ctx[BB];
__device__            int   g_ctr_v  [BB];

__device__ __forceinline__ float fast_tanh(float x) {
    float y;
    asm("tanh.approx.f32 %0, %1;" : "=f"(y) : "f"(x));
    return y;
}

// K1f: fused stage + dec_op1 GEMV
__global__ void k1f_dec1(const float* __restrict__ h, const float* __restrict__ c,
                         const float* __restrict__ dec_output,
                         const float* __restrict__ W, const float* __restrict__ bias) {
    __shared__ float sdec[32][129];
    __shared__ float sW[8][128];
    int t = threadIdx.x;
    int jj = t >> 5, b = t & 31;
    int j0 = blockIdx.x * 8;
    if (t < 128) {
        int i = blockIdx.x * 128 + t;
        int k = i >> 5, bb = i & 31;
        g_temp_t[i] = dec_output[bb * DD + k];
    }
    float acc = 0.f;
    for (int ch = 0; ch < 8; ch++) {
        int k0 = ch * 128;
        __syncthreads();
#pragma unroll
        for (int m = 0; m < 16; m++) {
            int e = m * 256 + t;
            int bb = e >> 7, kk = e & 127;
            int kg = k0 + kk;
            sdec[bb][kk] = (kg < DD) ? h[bb * DD + kg] : c[bb * DD + kg - DD];
        }
#pragma unroll
        for (int m = 0; m < 4; m++) {
            int e = m * 256 + t;
            int jx = e >> 7, kk = e & 127;
            sW[jx][kk] = W[(j0 + jx) * D2 + k0 + kk];
        }
        __syncthreads();
#pragma unroll 8
        for (int kk = 0; kk < 128; kk++)
            acc += sW[jj][kk] * sdec[b][kk];
    }
    g_dec1[b * D2 + j0 + jj] = acc + bias[j0 + jj];
}

// K2: scores — warp per row; also zeroes ctx counters for this replay
__global__ void k2_scores(const float4* __restrict__ enc1,
                          const float4* __restrict__ wattn) {
    __shared__ float4 sd1[256];
    __shared__ float4 swa[256];
    int t = threadIdx.x;
    if (blockIdx.x == 0 && t < BB) g_ctr_ctx[t] = 0;
    int row0 = blockIdx.x * 8;
    int b = row0 >> 10;
    sd1[t] = ((const float4*)g_dec1)[b * 256 + t];
    swa[t] = wattn[t];
    __syncthreads();
    int lane = t & 31, w = t >> 5;
    int row = row0 + w;
    float acc = 0.f;
#pragma unroll
    for (int i = 0; i < 8; i++) {
        int cidx = i * 32 + lane;
        float4 e  = enc1[(size_t)row * 256 + cidx];
        float4 dd = sd1[cidx];
        float4 wa = swa[cidx];
        acc += fast_tanh(e.x + dd.x) * wa.x;
        acc += fast_tanh(e.y + dd.y) * wa.y;
        acc += fast_tanh(e.z + dd.z) * wa.z;
        acc += fast_tanh(e.w + dd.w) * wa.w;
    }
#pragma unroll
    for (int o = 16; o; o >>= 1) acc += __shfl_down_sync(0xffffffffu, acc, o);
    if (!lane) g_scores[row] = acc;
}

// K4f: softmax (redundant per block) + context partial + LAST-BLOCK tail:
//      partial reduce + BN + temp_t + out_ctx + p_gen  (old k5)
__global__ void k4f_ctx(const float4* __restrict__ enc, const int* __restrict__ src,
                        float* __restrict__ out_attn,
                        const float* __restrict__ bn_m, const float* __restrict__ bn_v,
                        const float* __restrict__ gam,  const float* __restrict__ bet,
                        const float* __restrict__ Wp,   const float* __restrict__ bp,
                        const float* __restrict__ hh,   const float* __restrict__ cc,
                        const float* __restrict__ dinp, float* __restrict__ out_ctx) {
    int sc = blockIdx.x, b = blockIdx.y, t = threadIdx.x;
    __shared__ float satt[1024];
    __shared__ float sm[8];
    __shared__ float bc;
    __shared__ int slast;
    float4 s = ((const float4*)g_scores)[b * 256 + t];
    float m = fmaxf(fmaxf(s.x, s.y), fmaxf(s.z, s.w));
#pragma unroll
    for (int o = 16; o; o >>= 1) m = fmaxf(m, __shfl_down_sync(0xffffffffu, m, o));
    if (!(t & 31)) sm[t >> 5] = m;
    __syncthreads();
    if (t == 0) {
        float mm = sm[0];
#pragma unroll
        for (int i = 1; i < 8; i++) mm = fmaxf(mm, sm[i]);
        bc = mm;
    }
    __syncthreads();
    float mx = bc;
    __syncthreads();
    int4 id = ((const int4*)src)[b * 256 + t];
    float4 e;
    e.x = (id.x != 0) ? __expf(s.x - mx) : 0.f;
    e.y = (id.y != 0) ? __expf(s.y - mx) : 0.f;
    e.z = (id.z != 0) ? __expf(s.z - mx) : 0.f;
    e.w = (id.w != 0) ? __expf(s.w - mx) : 0.f;
    float sum = e.x + e.y + e.z + e.w;
#pragma unroll
    for (int o = 16; o; o >>= 1) sum += __shfl_down_sync(0xffffffffu, sum, o);
    if (!(t & 31)) sm[t >> 5] = sum;
    __syncthreads();
    if (t == 0) {
        float tt = 0.f;
#pragma unroll
        for (int i = 0; i < 8; i++) tt += sm[i];
        bc = 1.f / tt;
    }
    __syncthreads();
    float inv = bc;
    float4 a = make_float4(e.x * inv, e.y * inv, e.z * inv, e.w * inv);
    ((float4*)satt)[t] = a;
    __syncthreads();
    if (sc == 0) {
        ((float4*)g_attn)[b * 256 + t] = a;
        ((float4*)out_attn)[b * 256 + t] = a;
    }
    int s0 = sc * (SS / NSC);
    float4 acc = make_float4(0.f, 0.f, 0.f, 0.f);
    const float4* base = enc + (size_t)(b * SS + s0) * 256 + t;
#pragma unroll 8
    for (int ss = 0; ss < SS / NSC; ss++) {
        float  aa = satt[s0 + ss];
        float4 ee = base[(size_t)ss * 256];
        acc.x += aa * ee.x; acc.y += aa * ee.y; acc.z += aa * ee.z; acc.w += aa * ee.w;
    }
    ((float4*)g_ctxpart)[(sc * 32 + b) * 256 + t] = acc;
    // last-block tail for this b (old k5)
    __syncthreads();
    if (t == 0) {
        __threadfence();
        int old = atomicAdd(&g_ctr_ctx[b], 1);
        slast = (old == NSC - 1);
    }
    __syncthreads();
    if (!slast) return;
    __threadfence();
    float sv[4] = {0.f, 0.f, 0.f, 0.f};
#pragma unroll
    for (int scc = 0; scc < NSC; scc++) {
        float4 p = __ldcg(((const float4*)g_ctxpart) + (scc * 32 + b) * 256 + t);
        sv[0] += p.x; sv[1] += p.y; sv[2] += p.z; sv[3] += p.w;
    }
    int d = 4 * t;
    float ctx[4];
    float pp = 0.f;
#pragma unroll
    for (int i = 0; i < 4; i++) {
        int dd = d + i;
        float cx = (sv[i] - bn_m[dd]) * rsqrtf(bn_v[dd] + 1e-5f) * gam[dd] + bet[dd];
        ctx[i] = cx;
        g_temp_t[(DD + dd) * 32 + b] = cx;
        float dop = (dd < DD) ? hh[b * DD + dd] : cc[b * DD + dd - DD];
        pp += Wp[dd] * cx + Wp[D2 + dd] * dop;
    }
    ((float4*)out_ctx)[b * 256 + t] = make_float4(ctx[0], ctx[1], ctx[2], ctx[3]);
    if (t < 128) {
#pragma unroll
        for (int i = 0; i < 4; i++) {
            int dd = 4 * t + i;
            pp += Wp[2048 + dd] * dinp[b * DD + dd];
        }
    }
#pragma unroll
    for (int o = 16; o; o >>= 1) pp += __shfl_down_sync(0xffffffffu, pp, o);
    if (!(t & 31)) sm[t >> 5] = pp;
    __syncthreads();
    if (t == 0) {
        float tot = bp[0];
#pragma unroll
        for (int i = 0; i < 8; i++) tot += sm[i];
        g_pgen[b] = 1.f / (1.f + __expf(-tot));
    }
}

// K6: hidden = temp @ W_v1^T + b_v1  (128 blocks x 4 j)
__global__ void k6_hidden(const float* __restrict__ W, const float* __restrict__ bias) {
    int t = threadIdx.x;
    int b = t & 31, g = t >> 5;
    int j0 = blockIdx.x * 4;
    float acc[4];
#pragma unroll
    for (int jj = 0; jj < 4; jj++) acc[jj] = 0.f;
    int k0 = g * 192;
    for (int k = k0; k < k0 + 192; k++) {
        float x = g_temp_t[k * 32 + b];
#pragma unroll
        for (int jj = 0; jj < 4; jj++)
            acc[jj] += W[(j0 + jj) * D3 + k] * x;
    }
    __shared__ float sred[8][4][32];
#pragma unroll
    for (int jj = 0; jj < 4; jj++) sred[g][jj][b] = acc[jj];
    __syncthreads();
    if (t < 128) {
        int jj = t >> 5, bo = t & 31;
        float tot = bias[j0 + jj];
#pragma unroll
        for (int gg = 0; gg < 8; gg++) tot += sred[gg][jj][bo];
        g_hidden[bo * DD + j0 + jj] = tot;
    }
}

// K8a: vocab GEMM partials, split-K 2; zeroes sumtot/ctr for k8b
#define WSTR 20
__global__ __launch_bounds__(256) void k8a_logits(const float* __restrict__ Wv2) {
    __shared__ float Ws[256 * WSTR];
    __shared__ float Hs[32 * 16];
    int t  = threadIdx.x;
    if (blockIdx.x == 0 && blockIdx.y == 0 && t < BB) {
        g_sumtot[t] = 0.f;
        g_ctr_v[t] = 0;
    }
    int tv = t & 63, tb = t >> 6;
    int v0 = blockIdx.x * 256;
    int ks = blockIdx.y;
    int kbase = ks * 256;

    unsigned long long acc2[4][8];
#pragma unroll
    for (int j = 0; j < 4; j++)
#pragma unroll
        for (int bj = 0; bj < 8; bj++) acc2[j][bj] = 0ull;

    float4 wreg[4];
    float  hreg0, hreg1;
    {
        int k0 = kbase;
#pragma unroll
        for (int li = 0; li < 4; li++) {
            int flat = li * 256 + t;
            int v = flat >> 2, kq = flat & 3;
            int gv = v0 + v;
            wreg[li] = (gv < VV)
                ? *(const float4*)(Wv2 + (size_t)gv * DD + k0 + kq * 4)
                : make_float4(0.f, 0.f, 0.f, 0.f);
        }
        hreg0 = g_hidden[((t)       >> 4) * DD + k0 + ((t)       & 15)];
        hreg1 = g_hidden[((t + 256) >> 4) * DD + k0 + ((t + 256) & 15)];
    }
    {
#pragma unroll
        for (int li = 0; li < 4; li++) {
            int flat = li * 256 + t;
            int v = flat >> 2, kq = flat & 3;
            *(float4*)(Ws + v * WSTR + kq * 4) = wreg[li];
        }
        Hs[t] = hreg0;
        Hs[t + 256] = hreg1;
    }
    __syncthreads();

    for (int tile = 0; tile < 16; tile++) {
        if (tile < 15) {
            int k0 = kbase + (tile + 1) * 16;
#pragma unroll
            for (int li = 0; li < 4; li++) {
                int flat = li * 256 + t;
                int v = flat >> 2, kq = flat & 3;
                int gv = v0 + v;
                wreg[li] = (gv < VV)
                    ? *(const float4*)(Wv2 + (size_t)gv * DD + k0 + kq * 4)
                    : make_float4(0.f, 0.f, 0.f, 0.f);
            }
            hreg0 = g_hidden[((t)       >> 4) * DD + k0 + ((t)       & 15)];
            hreg1 = g_hidden[((t + 256) >> 4) * DD + k0 + ((t + 256) & 15)];
        }
#pragma unroll
        for (int kq = 0; kq < 4; kq++) {
            ulonglong2 h2[8];
#pragma unroll
            for (int bj = 0; bj < 8; bj++)
                h2[bj] = *(const ulonglong2*)(Hs + (tb * 8 + bj) * 16 + kq * 4);
#pragma unroll
            for (int j = 0; j < 4; j++) {
                ulonglong2 w2 = *(const ulonglong2*)(Ws + (tv + 64 * j) * WSTR + kq * 4);
#pragma unroll
                for (int bj = 0; bj < 8; bj++) {
                    asm("fma.rn.f32x2 %0, %1, %2, %0;"
                        : "+l"(acc2[j][bj]) : "l"(w2.x), "l"(h2[bj].x));
                    asm("fma.rn.f32x2 %0, %1, %2, %0;"
                        : "+l"(acc2[j][bj]) : "l"(w2.y), "l"(h2[bj].y));
                }
            }
        }
        if (tile < 15) {
            __syncthreads();
#pragma unroll
            for (int li = 0; li < 4; li++) {
                int flat = li * 256 + t;
                int v = flat >> 2, kq = flat & 3;
                *(float4*)(Ws + v * WSTR + kq * 4) = wreg[li];
            }
            Hs[t] = hreg0;
            Hs[t + 256] = hreg1;
            __syncthreads();
        }
    }
    float accf[4][8];
#pragma unroll
    for (int j = 0; j < 4; j++)
#pragma unroll
        for (int bj = 0; bj < 8; bj++) {
            unsigned long long a = acc2[j][bj];
            accf[j][bj] = __uint_as_float((unsigned)(a & 0xffffffffu)) +
                          __uint_as_float((unsigned)(a >> 32));
        }
#pragma unroll
    for (int p = 0; p < 2; p++) {
        __syncthreads();
        if ((tb >> 1) == p) {
#pragma unroll
            for (int j = 0; j < 4; j++)
#pragma unroll
                for (int bj = 0; bj < 8; bj++)
                    Ws[((tb & 1) * 8 + bj) * 256 + tv + 64 * j] = accf[j][bj];
        }
        __syncthreads();
#pragma unroll
        for (int i = 0; i < 4; i++) {
            int idx = i * 256 + t;
            int row = idx >> 6, col = idx & 63;
            *(float4*)(g_lpart + ((size_t)(ks * 32 + p * 16 + row) * VP + v0 + col * 4)) =
                *(const float4*)(Ws + row * 256 + col * 4);
        }
    }
}

// K8b: exp + per-b total sum (atomic) + LAST-BLOCK pre-scaled scatter.
// Covers all VF cols (OOV -> 0) so row b is fully initialized after this kernel.
__global__ void k8b_exp(const float* __restrict__ bv2, float* __restrict__ dout,
                        const int* __restrict__ src) {
    int b = blockIdx.x, cb = blockIdx.y, t = threadIdx.x;
    int base = cb * 2048;
    float sum = 0.f;
#pragma unroll
    for (int it = 0; it < 8; it++) {
        int v = base + it * 256 + t;
        if (v < VV) {
            float l = g_lpart[(size_t)b * VP + v] + g_lpart[(size_t)(32 + b) * VP + v] + bv2[v];
            float e = __expf(l);
            dout[(size_t)b * VF + v] = e;
            sum += e;
        } else if (v < VF) {
            dout[(size_t)b * VF + v] = 0.f;
        }
    }
    __shared__ float sm[8];
    __shared__ int slast;
#pragma unroll
    for (int o = 16; o; o >>= 1) sum += __shfl_down_sync(0xffffffffu, sum, o);
    if (!(t & 31)) sm[t >> 5] = sum;
    __syncthreads();
    if (t == 0) {
        float tot = 0.f;
#pragma unroll
        for (int i = 0; i < 8; i++) tot += sm[i];
        atomicAdd(&g_sumtot[b], tot);
        __threadfence();
        int old = atomicAdd(&g_ctr_v[b], 1);
        slast = (old == NCB - 1);
    }
    __syncthreads();
    if (!slast) return;
    __threadfence();
    float s = __ldcg(&g_sumtot[b]);
    float pg = g_pgen[b];
    float f = (1.f - pg) * s / pg;   // pre-scaled: k10f multiplies by pg/s
#pragma unroll
    for (int it = 0; it < 4; it++) {
        int si = it * 256 + t;
        int idx = src[b * SS + si];
        float val = f * g_attn[b * SS + si];
        atomicAdd(dout + (size_t)b * VF + idx, val);
    }
}

// K10f: scale by p_gen/sum (uniform, lands scatter adds exactly) + zero-fix
__global__ void k10f_finalize(float* __restrict__ dout) {
    int i0 = blockIdx.x * 256;
    int i = i0 + threadIdx.x;
    __shared__ float ssc[2];
    int bstart = i0 / VF;
    if (threadIdx.x < 2) {
        int b = bstart + (int)threadIdx.x;
        float sc = 0.f;
        if (b < BB) sc = g_pgen[b] / g_sumtot[b];
        ssc[threadIdx.x] = sc;
    }
    __syncthreads();
    int b = i / VF;
    float p = dout[i] * ssc[b - bstart];
    if (p == 0.f) p = 1e-12f;
    dout[i] = p;
}

extern "C" void kernel_launch(void* const* d_in, const int* in_sizes, int n_in,
                              void* d_out, int out_size) {
    const float* dec_output = (const float*)d_in[0];
    const float* hh         = (const float*)d_in[1];
    const float* cc         = (const float*)d_in[2];
    const float* dinp       = (const float*)d_in[3];
    const float* enc        = (const float*)d_in[4];
    const float* enc1       = (const float*)d_in[5];
    const int*   src        = (const int*)  d_in[6];
    const float* W_dec      = (const float*)d_in[7];
    const float* b_dec      = (const float*)d_in[8];
    const float* w_attn     = (const float*)d_in[9];
    const float* W_v1       = (const float*)d_in[10];
    const float* b_v1       = (const float*)d_in[11];
    const float* W_v2       = (const float*)d_in[12];
    const float* b_v2       = (const float*)d_in[13];
    const float* W_p        = (const float*)d_in[14];
    const float* b_p        = (const float*)d_in[15];
    const float* gam        = (const float*)d_in[16];
    const float* bet        = (const float*)d_in[17];
    const float* bn_m       = (const float*)d_in[18];
    const float* bn_v       = (const float*)d_in[19];

    float* dout     = (float*)d_out;
    float* out_attn = dout + BB * VF;
    float* out_ctx  = out_attn + BB * SS;

    k1f_dec1   <<<128, 256>>>(hh, cc, dec_output, W_dec, b_dec);
    k2_scores  <<<4096, 256>>>((const float4*)enc1, (const float4*)w_attn);
    k4f_ctx    <<<dim3(NSC, 32), 256>>>((const float4*)enc, src, out_attn,
                                        bn_m, bn_v, gam, bet, W_p, b_p,
                                        hh, cc, dinp, out_ctx);
    k6_hidden  <<<128, 256>>>(W_v1, b_v1);
    k8a_logits <<<dim3(192, 2), 256>>>(W_v2);
    k8b_exp    <<<dim3(32, NCB), 256>>>(b_v2, dout, src);
    k10f_finalize<<<6250, 256>>>(dout);
}

// round 6
// speedup vs baseline: 1.3578x; 1.1547x over previous
#include <cuda_runtime.h>

#define BB   32
#define SS   1024
#define DD   512
#define D2   1024
#define D3   1536
#define VV   49000
#define VP   49152
#define VF   50000
#define NCB  25
#define NSC  16
#define KB6  12      /* k6 split-K blocks */
#define JB6  4       /* k6 j blocks (128 j each) */

__device__ __align__(16) float g_temp_t [D3 * BB];
__device__ __align__(16) float g_dec1   [BB * D2];
__device__ __align__(16) float g_scores [BB * SS];
__device__ __align__(16) float g_attn   [BB * SS];
__device__ __align__(16) float g_ctxpart[NSC * BB * D2];
__device__ __align__(16) float g_hpart  [KB6 * BB * DD];
__device__ __align__(16) float g_hidden [BB * DD];
__device__            float g_pgen  [BB];
__device__ __align__(16) float g_lpart [2 * BB * VP];
__device__            float g_sumtot[BB];
__device__            int   g_ctr_ctx[BB];
__device__            int   g_ctr_v  [BB];
__device__            int   g_ctr_h  [JB6];

__device__ __forceinline__ float fast_tanh(float x) {
    float y;
    asm("tanh.approx.f32 %0, %1;" : "=f"(y) : "f"(x));
    return y;
}

// K1f: fused stage + dec_op1 GEMV (4-way split accumulator chain)
__global__ void k1f_dec1(const float* __restrict__ h, const float* __restrict__ c,
                         const float* __restrict__ dec_output,
                         const float* __restrict__ W, const float* __restrict__ bias) {
    __shared__ float sdec[32][129];
    __shared__ float sW[8][128];
    int t = threadIdx.x;
    int jj = t >> 5, b = t & 31;
    int j0 = blockIdx.x * 8;
    if (t < 128) {
        int i = blockIdx.x * 128 + t;
        int k = i >> 5, bb = i & 31;
        g_temp_t[i] = dec_output[bb * DD + k];
    }
    float a0 = 0.f, a1 = 0.f, a2 = 0.f, a3 = 0.f;
    for (int ch = 0; ch < 8; ch++) {
        int k0 = ch * 128;
        __syncthreads();
#pragma unroll
        for (int m = 0; m < 16; m++) {
            int e = m * 256 + t;
            int bb = e >> 7, kk = e & 127;
            int kg = k0 + kk;
            sdec[bb][kk] = (kg < DD) ? h[bb * DD + kg] : c[bb * DD + kg - DD];
        }
#pragma unroll
        for (int m = 0; m < 4; m++) {
            int e = m * 256 + t;
            int jx = e >> 7, kk = e & 127;
            sW[jx][kk] = W[(j0 + jx) * D2 + k0 + kk];
        }
        __syncthreads();
#pragma unroll
        for (int kk = 0; kk < 128; kk += 4) {
            a0 += sW[jj][kk + 0] * sdec[b][kk + 0];
            a1 += sW[jj][kk + 1] * sdec[b][kk + 1];
            a2 += sW[jj][kk + 2] * sdec[b][kk + 2];
            a3 += sW[jj][kk + 3] * sdec[b][kk + 3];
        }
    }
    g_dec1[b * D2 + j0 + jj] = (a0 + a1) + (a2 + a3) + bias[j0 + jj];
}

// K2: scores — warp per row; also zeroes counters for this replay
__global__ void k2_scores(const float4* __restrict__ enc1,
                          const float4* __restrict__ wattn) {
    __shared__ float4 sd1[256];
    __shared__ float4 swa[256];
    int t = threadIdx.x;
    if (blockIdx.x == 0 && t < BB) g_ctr_ctx[t] = 0;
    if (blockIdx.x == 1 && t < JB6) g_ctr_h[t] = 0;
    int row0 = blockIdx.x * 8;
    int b = row0 >> 10;
    sd1[t] = ((const float4*)g_dec1)[b * 256 + t];
    swa[t] = wattn[t];
    __syncthreads();
    int lane = t & 31, w = t >> 5;
    int row = row0 + w;
    float acc = 0.f;
#pragma unroll
    for (int i = 0; i < 8; i++) {
        int cidx = i * 32 + lane;
        float4 e  = enc1[(size_t)row * 256 + cidx];
        float4 dd = sd1[cidx];
        float4 wa = swa[cidx];
        acc += fast_tanh(e.x + dd.x) * wa.x;
        acc += fast_tanh(e.y + dd.y) * wa.y;
        acc += fast_tanh(e.z + dd.z) * wa.z;
        acc += fast_tanh(e.w + dd.w) * wa.w;
    }
#pragma unroll
    for (int o = 16; o; o >>= 1) acc += __shfl_down_sync(0xffffffffu, acc, o);
    if (!lane) g_scores[row] = acc;
}

// K4f: softmax + context partial + last-block tail (BN + temp_t + ctx + p_gen)
__global__ void k4f_ctx(const float4* __restrict__ enc, const int* __restrict__ src,
                        float* __restrict__ out_attn,
                        const float* __restrict__ bn_m, const float* __restrict__ bn_v,
                        const float* __restrict__ gam,  const float* __restrict__ bet,
                        const float* __restrict__ Wp,   const float* __restrict__ bp,
                        const float* __restrict__ hh,   const float* __restrict__ cc,
                        const float* __restrict__ dinp, float* __restrict__ out_ctx) {
    int sc = blockIdx.x, b = blockIdx.y, t = threadIdx.x;
    __shared__ float satt[1024];
    __shared__ float sm[8];
    __shared__ float bc;
    __shared__ int slast;
    float4 s = ((const float4*)g_scores)[b * 256 + t];
    float m = fmaxf(fmaxf(s.x, s.y), fmaxf(s.z, s.w));
#pragma unroll
    for (int o = 16; o; o >>= 1) m = fmaxf(m, __shfl_down_sync(0xffffffffu, m, o));
    if (!(t & 31)) sm[t >> 5] = m;
    __syncthreads();
    if (t == 0) {
        float mm = sm[0];
#pragma unroll
        for (int i = 1; i < 8; i++) mm = fmaxf(mm, sm[i]);
        bc = mm;
    }
    __syncthreads();
    float mx = bc;
    __syncthreads();
    int4 id = ((const int4*)src)[b * 256 + t];
    float4 e;
    e.x = (id.x != 0) ? __expf(s.x - mx) : 0.f;
    e.y = (id.y != 0) ? __expf(s.y - mx) : 0.f;
    e.z = (id.z != 0) ? __expf(s.z - mx) : 0.f;
    e.w = (id.w != 0) ? __expf(s.w - mx) : 0.f;
    float sum = e.x + e.y + e.z + e.w;
#pragma unroll
    for (int o = 16; o; o >>= 1) sum += __shfl_down_sync(0xffffffffu, sum, o);
    if (!(t & 31)) sm[t >> 5] = sum;
    __syncthreads();
    if (t == 0) {
        float tt = 0.f;
#pragma unroll
        for (int i = 0; i < 8; i++) tt += sm[i];
        bc = 1.f / tt;
    }
    __syncthreads();
    float inv = bc;
    float4 a = make_float4(e.x * inv, e.y * inv, e.z * inv, e.w * inv);
    ((float4*)satt)[t] = a;
    __syncthreads();
    if (sc == 0) {
        ((float4*)g_attn)[b * 256 + t] = a;
        ((float4*)out_attn)[b * 256 + t] = a;
    }
    int s0 = sc * (SS / NSC);
    float4 acc = make_float4(0.f, 0.f, 0.f, 0.f);
    const float4* base = enc + (size_t)(b * SS + s0) * 256 + t;
#pragma unroll 8
    for (int ss = 0; ss < SS / NSC; ss++) {
        float  aa = satt[s0 + ss];
        float4 ee = base[(size_t)ss * 256];
        acc.x += aa * ee.x; acc.y += aa * ee.y; acc.z += aa * ee.z; acc.w += aa * ee.w;
    }
    ((float4*)g_ctxpart)[(sc * 32 + b) * 256 + t] = acc;
    __syncthreads();
    if (t == 0) {
        __threadfence();
        int old = atomicAdd(&g_ctr_ctx[b], 1);
        slast = (old == NSC - 1);
    }
    __syncthreads();
    if (!slast) return;
    __threadfence();
    float sv[4] = {0.f, 0.f, 0.f, 0.f};
#pragma unroll
    for (int scc = 0; scc < NSC; scc++) {
        float4 p = __ldcg(((const float4*)g_ctxpart) + (scc * 32 + b) * 256 + t);
        sv[0] += p.x; sv[1] += p.y; sv[2] += p.z; sv[3] += p.w;
    }
    int d = 4 * t;
    float ctx[4];
    float pp = 0.f;
#pragma unroll
    for (int i = 0; i < 4; i++) {
        int dd = d + i;
        float cx = (sv[i] - bn_m[dd]) * rsqrtf(bn_v[dd] + 1e-5f) * gam[dd] + bet[dd];
        ctx[i] = cx;
        g_temp_t[(DD + dd) * 32 + b] = cx;
        float dop = (dd < DD) ? hh[b * DD + dd] : cc[b * DD + dd - DD];
        pp += Wp[dd] * cx + Wp[D2 + dd] * dop;
    }
    ((float4*)out_ctx)[b * 256 + t] = make_float4(ctx[0], ctx[1], ctx[2], ctx[3]);
    if (t < 128) {
#pragma unroll
        for (int i = 0; i < 4; i++) {
            int dd = 4 * t + i;
            pp += Wp[2048 + dd] * dinp[b * DD + dd];
        }
    }
#pragma unroll
    for (int o = 16; o; o >>= 1) pp += __shfl_down_sync(0xffffffffu, pp, o);
    if (!(t & 31)) sm[t >> 5] = pp;
    __syncthreads();
    if (t == 0) {
        float tot = bp[0];
#pragma unroll
        for (int i = 0; i < 8; i++) tot += sm[i];
        g_pgen[b] = 1.f / (1.f + __expf(-tot));
    }
}

// K6: hidden = temp @ W_v1^T + b_v1 — register-blocked split-K GEMM.
// Grid (JB6=4, KB6=12); block 128j x 32b x 128k; thread 2j x 8b, f32x2 accs.
// Last k-block per jb combines partials + bias deterministically.
#define XS6 68
__global__ __launch_bounds__(256) void k6_hidden(const float* __restrict__ W,
                                                 const float* __restrict__ bias) {
    __shared__ float sW[128 * XS6];
    __shared__ float sX[32 * XS6];
    int t = threadIdx.x;
    int tj = t & 63, tb = t >> 6;
    int jb = blockIdx.x, kb = blockIdx.y;
    int j0 = jb * 128;
    __shared__ int slast;

    unsigned long long acc2[2][8];
#pragma unroll
    for (int jr = 0; jr < 2; jr++)
#pragma unroll
        for (int bj = 0; bj < 8; bj++) acc2[jr][bj] = 0ull;

#pragma unroll
    for (int sub = 0; sub < 2; sub++) {
        int k0s = kb * 128 + sub * 64;
        __syncthreads();
        // stage W: 128 rows x 64 k
#pragma unroll
        for (int li = 0; li < 8; li++) {
            int flat = li * 256 + t;
            int row = flat >> 4, kc = flat & 15;
            float4 f = *(const float4*)(W + (size_t)(j0 + row) * D3 + k0s + kc * 4);
            *(float4*)(sW + row * XS6 + kc * 4) = f;
        }
        // stage X: 64 k x 32 b from transposed temp_t
#pragma unroll
        for (int li = 0; li < 2; li++) {
            int flat = li * 256 + t;
            int kk = flat >> 3, bq = flat & 7;
            float4 f = ((const float4*)g_temp_t)[(size_t)(k0s + kk) * 8 + bq];
            sX[(bq * 4 + 0) * XS6 + kk] = f.x;
            sX[(bq * 4 + 1) * XS6 + kk] = f.y;
            sX[(bq * 4 + 2) * XS6 + kk] = f.z;
            sX[(bq * 4 + 3) * XS6 + kk] = f.w;
        }
        __syncthreads();
#pragma unroll
        for (int kq = 0; kq < 16; kq++) {
            ulonglong2 xv[8];
#pragma unroll
            for (int bj = 0; bj < 8; bj++)
                xv[bj] = *(const ulonglong2*)(sX + (tb * 8 + bj) * XS6 + kq * 4);
#pragma unroll
            for (int jr = 0; jr < 2; jr++) {
                ulonglong2 wv = *(const ulonglong2*)(sW + (jr * 64 + tj) * XS6 + kq * 4);
#pragma unroll
                for (int bj = 0; bj < 8; bj++) {
                    asm("fma.rn.f32x2 %0, %1, %2, %0;"
                        : "+l"(acc2[jr][bj]) : "l"(wv.x), "l"(xv[bj].x));
                    asm("fma.rn.f32x2 %0, %1, %2, %0;"
                        : "+l"(acc2[jr][bj]) : "l"(wv.y), "l"(xv[bj].y));
                }
            }
        }
    }
    // write partials
#pragma unroll
    for (int jr = 0; jr < 2; jr++)
#pragma unroll
        for (int bj = 0; bj < 8; bj++) {
            unsigned long long a = acc2[jr][bj];
            float v = __uint_as_float((unsigned)(a & 0xffffffffu)) +
                      __uint_as_float((unsigned)(a >> 32));
            g_hpart[((size_t)kb * 32 + tb * 8 + bj) * DD + j0 + jr * 64 + tj] = v;
        }
    __syncthreads();
    if (t == 0) {
        __threadfence();
        int old = atomicAdd(&g_ctr_h[jb], 1);
        slast = (old == KB6 - 1);
    }
    __syncthreads();
    if (!slast) return;
    __threadfence();
    // combine: 32 b x 128 j region, fixed-order sum over 12 partials + bias
#pragma unroll
    for (int li = 0; li < 4; li++) {
        int flat = li * 256 + t;
        int b = flat >> 5, jq = flat & 31;       // jq indexes float4 within 128 j
        float4 sum = *(const float4*)(bias + j0 + jq * 4);
#pragma unroll
        for (int p = 0; p < KB6; p++) {
            float4 v = __ldcg((const float4*)(g_hpart + ((size_t)p * 32 + b) * DD + j0 + jq * 4));
            sum.x += v.x; sum.y += v.y; sum.z += v.z; sum.w += v.w;
        }
        *(float4*)(g_hidden + (size_t)b * DD + j0 + jq * 4) = sum;
    }
}

// K8a: vocab GEMM partials, split-K 2; zeroes sumtot/ctr for k8b
#define WSTR 20
__global__ __launch_bounds__(256) void k8a_logits(const float* __restrict__ Wv2) {
    __shared__ float Ws[256 * WSTR];
    __shared__ float Hs[32 * 16];
    int t  = threadIdx.x;
    if (blockIdx.x == 0 && blockIdx.y == 0 && t < BB) {
        g_sumtot[t] = 0.f;
        g_ctr_v[t] = 0;
    }
    int tv = t & 63, tb = t >> 6;
    int v0 = blockIdx.x * 256;
    int ks = blockIdx.y;
    int kbase = ks * 256;

    unsigned long long acc2[4][8];
#pragma unroll
    for (int j = 0; j < 4; j++)
#pragma unroll
        for (int bj = 0; bj < 8; bj++) acc2[j][bj] = 0ull;

    float4 wreg[4];
    float  hreg0, hreg1;
    {
        int k0 = kbase;
#pragma unroll
        for (int li = 0; li < 4; li++) {
            int flat = li * 256 + t;
            int v = flat >> 2, kq = flat & 3;
            int gv = v0 + v;
            wreg[li] = (gv < VV)
                ? *(const float4*)(Wv2 + (size_t)gv * DD + k0 + kq * 4)
                : make_float4(0.f, 0.f, 0.f, 0.f);
        }
        hreg0 = g_hidden[((t)       >> 4) * DD + k0 + ((t)       & 15)];
        hreg1 = g_hidden[((t + 256) >> 4) * DD + k0 + ((t + 256) & 15)];
    }
    {
#pragma unroll
        for (int li = 0; li < 4; li++) {
            int flat = li * 256 + t;
            int v = flat >> 2, kq = flat & 3;
            *(float4*)(Ws + v * WSTR + kq * 4) = wreg[li];
        }
        Hs[t] = hreg0;
        Hs[t + 256] = hreg1;
    }
    __syncthreads();

    for (int tile = 0; tile < 16; tile++) {
        if (tile < 15) {
            int k0 = kbase + (tile + 1) * 16;
#pragma unroll
            for (int li = 0; li < 4; li++) {
                int flat = li * 256 + t;
                int v = flat >> 2, kq = flat & 3;
                int gv = v0 + v;
                wreg[li] = (gv < VV)
                    ? *(const float4*)(Wv2 + (size_t)gv * DD + k0 + kq * 4)
                    : make_float4(0.f, 0.f, 0.f, 0.f);
            }
            hreg0 = g_hidden[((t)       >> 4) * DD + k0 + ((t)       & 15)];
            hreg1 = g_hidden[((t + 256) >> 4) * DD + k0 + ((t + 256) & 15)];
        }
#pragma unroll
        for (int kq = 0; kq < 4; kq++) {
            ulonglong2 h2[8];
#pragma unroll
            for (int bj = 0; bj < 8; bj++)
                h2[bj] = *(const ulonglong2*)(Hs + (tb * 8 + bj) * 16 + kq * 4);
#pragma unroll
            for (int j = 0; j < 4; j++) {
                ulonglong2 w2 = *(const ulonglong2*)(Ws + (tv + 64 * j) * WSTR + kq * 4);
#pragma unroll
                for (int bj = 0; bj < 8; bj++) {
                    asm("fma.rn.f32x2 %0, %1, %2, %0;"
                        : "+l"(acc2[j][bj]) : "l"(w2.x), "l"(h2[bj].x));
                    asm("fma.rn.f32x2 %0, %1, %2, %0;"
                        : "+l"(acc2[j][bj]) : "l"(w2.y), "l"(h2[bj].y));
                }
            }
        }
        if (tile < 15) {
            __syncthreads();
#pragma unroll
            for (int li = 0; li < 4; li++) {
                int flat = li * 256 + t;
                int v = flat >> 2, kq = flat & 3;
                *(float4*)(Ws + v * WSTR + kq * 4) = wreg[li];
            }
            Hs[t] = hreg0;
            Hs[t + 256] = hreg1;
            __syncthreads();
        }
    }
    float accf[4][8];
#pragma unroll
    for (int j = 0; j < 4; j++)
#pragma unroll
        for (int bj = 0; bj < 8; bj++) {
            unsigned long long a = acc2[j][bj];
            accf[j][bj] = __uint_as_float((unsigned)(a & 0xffffffffu)) +
                          __uint_as_float((unsigned)(a >> 32));
        }
#pragma unroll
    for (int p = 0; p < 2; p++) {
        __syncthreads();
        if ((tb >> 1) == p) {
#pragma unroll
            for (int j = 0; j < 4; j++)
#pragma unroll
                for (int bj = 0; bj < 8; bj++)
                    Ws[((tb & 1) * 8 + bj) * 256 + tv + 64 * j] = accf[j][bj];
        }
        __syncthreads();
#pragma unroll
        for (int i = 0; i < 4; i++) {
            int idx = i * 256 + t;
            int row = idx >> 6, col = idx & 63;
            *(float4*)(g_lpart + ((size_t)(ks * 32 + p * 16 + row) * VP + v0 + col * 4)) =
                *(const float4*)(Ws + row * 256 + col * 4);
        }
    }
}

// K8b: exp + per-b sum + last-block pre-scaled scatter; initializes OOV cols
__global__ void k8b_exp(const float* __restrict__ bv2, float* __restrict__ dout,
                        const int* __restrict__ src) {
    int b = blockIdx.x, cb = blockIdx.y, t = threadIdx.x;
    int base = cb * 2048;
    float sum = 0.f;
#pragma unroll
    for (int it = 0; it < 8; it++) {
        int v = base + it * 256 + t;
        if (v < VV) {
            float l = g_lpart[(size_t)b * VP + v] + g_lpart[(size_t)(32 + b) * VP + v] + bv2[v];
            float e = __expf(l);
            dout[(size_t)b * VF + v] = e;
            sum += e;
        } else if (v < VF) {
            dout[(size_t)b * VF + v] = 0.f;
        }
    }
    __shared__ float sm[8];
    __shared__ int slast;
#pragma unroll
    for (int o = 16; o; o >>= 1) sum += __shfl_down_sync(0xffffffffu, sum, o);
    if (!(t & 31)) sm[t >> 5] = sum;
    __syncthreads();
    if (t == 0) {
        float tot = 0.f;
#pragma unroll
        for (int i = 0; i < 8; i++) tot += sm[i];
        atomicAdd(&g_sumtot[b], tot);
        __threadfence();
        int old = atomicAdd(&g_ctr_v[b], 1);
        slast = (old == NCB - 1);
    }
    __syncthreads();
    if (!slast) return;
    __threadfence();
    float s = __ldcg(&g_sumtot[b]);
    float pg = g_pgen[b];
    float f = (1.f - pg) * s / pg;
#pragma unroll
    for (int it = 0; it < 4; it++) {
        int si = it * 256 + t;
        int idx = src[b * SS + si];
        float val = f * g_attn[b * SS + si];
        atomicAdd(dout + (size_t)b * VF + idx, val);
    }
}

// K10f: uniform scale p_gen/sum + zero-fix
__global__ void k10f_finalize(float* __restrict__ dout) {
    int i0 = blockIdx.x * 256;
    int i = i0 + threadIdx.x;
    __shared__ float ssc[2];
    int bstart = i0 / VF;
    if (threadIdx.x < 2) {
        int b = bstart + (int)threadIdx.x;
        float sc = 0.f;
        if (b < BB) sc = g_pgen[b] / g_sumtot[b];
        ssc[threadIdx.x] = sc;
    }
    __syncthreads();
    int b = i / VF;
    float p = dout[i] * ssc[b - bstart];
    if (p == 0.f) p = 1e-12f;
    dout[i] = p;
}

extern "C" void kernel_launch(void* const* d_in, const int* in_sizes, int n_in,
                              void* d_out, int out_size) {
    const float* dec_output = (const float*)d_in[0];
    const float* hh         = (const float*)d_in[1];
    const float* cc         = (const float*)d_in[2];
    const float* dinp       = (const float*)d_in[3];
    const float* enc        = (const float*)d_in[4];
    const float* enc1       = (const float*)d_in[5];
    const int*   src        = (const int*)  d_in[6];
    const float* W_dec      = (const float*)d_in[7];
    const float* b_dec      = (const float*)d_in[8];
    const float* w_attn     = (const float*)d_in[9];
    const float* W_v1       = (const float*)d_in[10];
    const float* b_v1       = (const float*)d_in[11];
    const float* W_v2       = (const float*)d_in[12];
    const float* b_v2       = (const float*)d_in[13];
    const float* W_p        = (const float*)d_in[14];
    const float* b_p        = (const float*)d_in[15];
    const float* gam        = (const float*)d_in[16];
    const float* bet        = (const float*)d_in[17];
    const float* bn_m       = (const float*)d_in[18];
    const float* bn_v       = (const float*)d_in[19];

    float* dout     = (float*)d_out;
    float* out_attn = dout + BB * VF;
    float* out_ctx  = out_attn + BB * SS;

    k1f_dec1   <<<128, 256>>>(hh, cc, dec_output, W_dec, b_dec);
    k2_scores  <<<4096, 256>>>((const float4*)enc1, (const float4*)w_attn);
    k4f_ctx    <<<dim3(NSC, 32), 256>>>((const float4*)enc, src, out_attn,
                                        bn_m, bn_v, gam, bet, W_p, b_p,
                                        hh, cc, dinp, out_ctx);
    k6_hidden  <<<dim3(JB6, KB6), 256>>>(W_v1, b_v1);
    k8a_logits <<<dim3(192, 2), 256>>>(W_v2);
    k8b_exp    <<<dim3(32, NCB), 256>>>(b_v2, dout, src);
    k10f_finalize<<<6250, 256>>>(dout);
}

// round 7
// speedup vs baseline: 1.3860x; 1.0208x over previous
#include <cuda_runtime.h>

#define BB   32
#define SS   1024
#define DD   512
#define D2   1024
#define D3   1536
#define VV   49000
#define VP   49152
#define VF   50000
#define NCB  25
#define NSC  16
#define KB6  12
#define JB6  4

__device__ __align__(16) float g_temp_t [D3 * BB];
__device__ __align__(16) float g_dec1   [BB * D2];
__device__ __align__(16) float g_scores [BB * SS];
__device__ __align__(16) float g_attn   [BB * SS];
__device__ __align__(16) float g_ctxpart[NSC * BB * D2];
__device__ __align__(16) float g_hpart  [KB6 * BB * DD];
__device__ __align__(16) float g_hidden [BB * DD];
__device__            float g_pgen  [BB];
__device__ __align__(16) float g_lpart [2 * BB * VP];
__device__            float g_sumtot[BB];
__device__            int   g_ctr_dec1;
__device__            int   g_ctr_ctx[BB];
__device__            int   g_ctr_v  [BB];
__device__            int   g_ctr_h  [JB6];
__device__            int   g_hready;

__device__ __forceinline__ float fast_tanh(float x) {
    float y;
    asm("tanh.approx.f32 %0, %1;" : "=f"(y) : "f"(x));
    return y;
}

// ===========================================================================
// A: fused k1f (dec1 GEMV, bids 0..127) + k2 (scores, bids 128..4223)
// ===========================================================================
__global__ void kA_dec1_scores(const float* __restrict__ h, const float* __restrict__ c,
                               const float* __restrict__ dec_output,
                               const float* __restrict__ W, const float* __restrict__ bias,
                               const float4* __restrict__ enc1,
                               const float4* __restrict__ wattn) {
    __shared__ __align__(16) float abuf[5152];
    int t = threadIdx.x;
    int bid = blockIdx.x;

    if (bid < 128) {
        // ---- k1f part ----
        if (bid == 0 && t < BB) g_ctr_ctx[t] = 0;
        float* sdec = abuf;            // [32][129]
        float* sW   = abuf + 4128;     // [8][128]
        int jj = t >> 5, b = t & 31;
        int j0 = bid * 8;
        if (t < 128) {
            int i = bid * 128 + t;
            int k = i >> 5, bb = i & 31;
            g_temp_t[i] = dec_output[bb * DD + k];
        }
        float a0 = 0.f, a1 = 0.f, a2 = 0.f, a3 = 0.f;
        for (int ch = 0; ch < 8; ch++) {
            int k0 = ch * 128;
            __syncthreads();
#pragma unroll
            for (int m = 0; m < 16; m++) {
                int e = m * 256 + t;
                int bb = e >> 7, kk = e & 127;
                int kg = k0 + kk;
                sdec[bb * 129 + kk] = (kg < DD) ? h[bb * DD + kg] : c[bb * DD + kg - DD];
            }
#pragma unroll
            for (int m = 0; m < 4; m++) {
                int e = m * 256 + t;
                int jx = e >> 7, kk = e & 127;
                sW[jx * 128 + kk] = W[(j0 + jx) * D2 + k0 + kk];
            }
            __syncthreads();
#pragma unroll
            for (int kk = 0; kk < 128; kk += 4) {
                a0 += sW[jj * 128 + kk + 0] * sdec[b * 129 + kk + 0];
                a1 += sW[jj * 128 + kk + 1] * sdec[b * 129 + kk + 1];
                a2 += sW[jj * 128 + kk + 2] * sdec[b * 129 + kk + 2];
                a3 += sW[jj * 128 + kk + 3] * sdec[b * 129 + kk + 3];
            }
        }
        g_dec1[b * D2 + j0 + jj] = (a0 + a1) + (a2 + a3) + bias[j0 + jj];
        __threadfence();
        __syncthreads();
        if (t == 0) atomicAdd(&g_ctr_dec1, 1);
        return;
    }

    // ---- k2 part ----
    float4* sd1 = (float4*)abuf;          // [256]
    float4* swa = ((float4*)abuf) + 256;  // [256]
    int row0 = (bid - 128) * 8;
    int b = row0 >> 10;
    swa[t] = wattn[t];
    int lane = t & 31, w = t >> 5;
    int row = row0 + w;
    // prefetch enc1 into registers BEFORE waiting on dec1
    float4 e[8];
#pragma unroll
    for (int i = 0; i < 8; i++)
        e[i] = enc1[(size_t)row * 256 + i * 32 + lane];
    if (t == 0) {
        while (*(volatile int*)&g_ctr_dec1 < 128) __nanosleep(64);
    }
    __syncthreads();
    __threadfence();
    sd1[t] = __ldcg(((const float4*)g_dec1) + b * 256 + t);
    __syncthreads();
    float acc = 0.f;
#pragma unroll
    for (int i = 0; i < 8; i++) {
        int cidx = i * 32 + lane;
        float4 dd = sd1[cidx];
        float4 wa = swa[cidx];
        acc += fast_tanh(e[i].x + dd.x) * wa.x;
        acc += fast_tanh(e[i].y + dd.y) * wa.y;
        acc += fast_tanh(e[i].z + dd.z) * wa.z;
        acc += fast_tanh(e[i].w + dd.w) * wa.w;
    }
#pragma unroll
    for (int o = 16; o; o >>= 1) acc += __shfl_down_sync(0xffffffffu, acc, o);
    if (!lane) g_scores[row] = acc;
}

// ===========================================================================
// B: k4f — softmax + context partial + last-block tail (BN + ctx + p_gen)
// ===========================================================================
__global__ void kB_ctx(const float4* __restrict__ enc, const int* __restrict__ src,
                       float* __restrict__ out_attn,
                       const float* __restrict__ bn_m, const float* __restrict__ bn_v,
                       const float* __restrict__ gam,  const float* __restrict__ bet,
                       const float* __restrict__ Wp,   const float* __restrict__ bp,
                       const float* __restrict__ hh,   const float* __restrict__ cc,
                       const float* __restrict__ dinp, float* __restrict__ out_ctx) {
    int sc = blockIdx.x, b = blockIdx.y, t = threadIdx.x;
    __shared__ float satt[1024];
    __shared__ float sm[8];
    __shared__ float bc;
    __shared__ int slast;
    if (sc == 0 && b == 0) {
        if (t == 0) { g_ctr_dec1 = 0; g_hready = 0; }
        if (t < JB6) g_ctr_h[t] = 0;
    }
    float4 s = ((const float4*)g_scores)[b * 256 + t];
    float m = fmaxf(fmaxf(s.x, s.y), fmaxf(s.z, s.w));
#pragma unroll
    for (int o = 16; o; o >>= 1) m = fmaxf(m, __shfl_down_sync(0xffffffffu, m, o));
    if (!(t & 31)) sm[t >> 5] = m;
    __syncthreads();
    if (t == 0) {
        float mm = sm[0];
#pragma unroll
        for (int i = 1; i < 8; i++) mm = fmaxf(mm, sm[i]);
        bc = mm;
    }
    __syncthreads();
    float mx = bc;
    __syncthreads();
    int4 id = ((const int4*)src)[b * 256 + t];
    float4 e;
    e.x = (id.x != 0) ? __expf(s.x - mx) : 0.f;
    e.y = (id.y != 0) ? __expf(s.y - mx) : 0.f;
    e.z = (id.z != 0) ? __expf(s.z - mx) : 0.f;
    e.w = (id.w != 0) ? __expf(s.w - mx) : 0.f;
    float sum = e.x + e.y + e.z + e.w;
#pragma unroll
    for (int o = 16; o; o >>= 1) sum += __shfl_down_sync(0xffffffffu, sum, o);
    if (!(t & 31)) sm[t >> 5] = sum;
    __syncthreads();
    if (t == 0) {
        float tt = 0.f;
#pragma unroll
        for (int i = 0; i < 8; i++) tt += sm[i];
        bc = 1.f / tt;
    }
    __syncthreads();
    float inv = bc;
    float4 a = make_float4(e.x * inv, e.y * inv, e.z * inv, e.w * inv);
    ((float4*)satt)[t] = a;
    __syncthreads();
    if (sc == 0) {
        ((float4*)g_attn)[b * 256 + t] = a;
        ((float4*)out_attn)[b * 256 + t] = a;
    }
    int s0 = sc * (SS / NSC);
    float4 acc = make_float4(0.f, 0.f, 0.f, 0.f);
    const float4* base = enc + (size_t)(b * SS + s0) * 256 + t;
#pragma unroll 8
    for (int ss = 0; ss < SS / NSC; ss++) {
        float  aa = satt[s0 + ss];
        float4 ee = base[(size_t)ss * 256];
        acc.x += aa * ee.x; acc.y += aa * ee.y; acc.z += aa * ee.z; acc.w += aa * ee.w;
    }
    ((float4*)g_ctxpart)[(sc * 32 + b) * 256 + t] = acc;
    __syncthreads();
    if (t == 0) {
        __threadfence();
        int old = atomicAdd(&g_ctr_ctx[b], 1);
        slast = (old == NSC - 1);
    }
    __syncthreads();
    if (!slast) return;
    __threadfence();
    float sv[4] = {0.f, 0.f, 0.f, 0.f};
#pragma unroll
    for (int scc = 0; scc < NSC; scc++) {
        float4 p = __ldcg(((const float4*)g_ctxpart) + (scc * 32 + b) * 256 + t);
        sv[0] += p.x; sv[1] += p.y; sv[2] += p.z; sv[3] += p.w;
    }
    int d = 4 * t;
    float ctx[4];
    float pp = 0.f;
#pragma unroll
    for (int i = 0; i < 4; i++) {
        int dd = d + i;
        float cx = (sv[i] - bn_m[dd]) * rsqrtf(bn_v[dd] + 1e-5f) * gam[dd] + bet[dd];
        ctx[i] = cx;
        g_temp_t[(DD + dd) * 32 + b] = cx;
        float dop = (dd < DD) ? hh[b * DD + dd] : cc[b * DD + dd - DD];
        pp += Wp[dd] * cx + Wp[D2 + dd] * dop;
    }
    ((float4*)out_ctx)[b * 256 + t] = make_float4(ctx[0], ctx[1], ctx[2], ctx[3]);
    if (t < 128) {
#pragma unroll
        for (int i = 0; i < 4; i++) {
            int dd = 4 * t + i;
            pp += Wp[2048 + dd] * dinp[b * DD + dd];
        }
    }
#pragma unroll
    for (int o = 16; o; o >>= 1) pp += __shfl_down_sync(0xffffffffu, pp, o);
    if (!(t & 31)) sm[t >> 5] = pp;
    __syncthreads();
    if (t == 0) {
        float tot = bp[0];
#pragma unroll
        for (int i = 0; i < 8; i++) tot += sm[i];
        g_pgen[b] = 1.f / (1.f + __expf(-tot));
    }
}

// ===========================================================================
// C: fused k6 (hidden GEMM, bids 0..47) + k8a (vocab logits, bids 48..431)
// ===========================================================================
#define XS6  68
#define WSTR 20
__global__ void __launch_bounds__(256, 2)
kC_hidden_logits(const float* __restrict__ Wv1, const float* __restrict__ bv1,
                 const float* __restrict__ Wv2) {
    __shared__ __align__(16) float cbuf[10880];
    __shared__ int slast;
    int t = threadIdx.x;
    int bid = blockIdx.x;

    if (bid < 48) {
        // ---- k6 part: hidden = temp @ W_v1^T + b_v1 ----
        float* sW = cbuf;                 // 128 x XS6
        float* sX = cbuf + 128 * XS6;     // 32 x XS6
        int tj = t & 63, tb = t >> 6;
        int jb = bid & 3, kb = bid >> 2;
        int j0 = jb * 128;
        unsigned long long acc2[2][8];
#pragma unroll
        for (int jr = 0; jr < 2; jr++)
#pragma unroll
            for (int bj = 0; bj < 8; bj++) acc2[jr][bj] = 0ull;
#pragma unroll
        for (int sub = 0; sub < 2; sub++) {
            int k0s = kb * 128 + sub * 64;
            __syncthreads();
#pragma unroll
            for (int li = 0; li < 8; li++) {
                int flat = li * 256 + t;
                int row = flat >> 4, kc = flat & 15;
                float4 f = *(const float4*)(Wv1 + (size_t)(j0 + row) * D3 + k0s + kc * 4);
                *(float4*)(sW + row * XS6 + kc * 4) = f;
            }
#pragma unroll
            for (int li = 0; li < 2; li++) {
                int flat = li * 256 + t;
                int kk = flat >> 3, bq = flat & 7;
                float4 f = ((const float4*)g_temp_t)[(size_t)(k0s + kk) * 8 + bq];
                sX[(bq * 4 + 0) * XS6 + kk] = f.x;
                sX[(bq * 4 + 1) * XS6 + kk] = f.y;
                sX[(bq * 4 + 2) * XS6 + kk] = f.z;
                sX[(bq * 4 + 3) * XS6 + kk] = f.w;
            }
            __syncthreads();
#pragma unroll
            for (int kq = 0; kq < 16; kq++) {
                ulonglong2 xv[8];
#pragma unroll
                for (int bj = 0; bj < 8; bj++)
                    xv[bj] = *(const ulonglong2*)(sX + (tb * 8 + bj) * XS6 + kq * 4);
#pragma unroll
                for (int jr = 0; jr < 2; jr++) {
                    ulonglong2 wv = *(const ulonglong2*)(sW + (jr * 64 + tj) * XS6 + kq * 4);
#pragma unroll
                    for (int bj = 0; bj < 8; bj++) {
                        asm("fma.rn.f32x2 %0, %1, %2, %0;"
                            : "+l"(acc2[jr][bj]) : "l"(wv.x), "l"(xv[bj].x));
                        asm("fma.rn.f32x2 %0, %1, %2, %0;"
                            : "+l"(acc2[jr][bj]) : "l"(wv.y), "l"(xv[bj].y));
                    }
                }
            }
        }
#pragma unroll
        for (int jr = 0; jr < 2; jr++)
#pragma unroll
            for (int bj = 0; bj < 8; bj++) {
                unsigned long long a = acc2[jr][bj];
                float v = __uint_as_float((unsigned)(a & 0xffffffffu)) +
                          __uint_as_float((unsigned)(a >> 32));
                g_hpart[((size_t)kb * 32 + tb * 8 + bj) * DD + j0 + jr * 64 + tj] = v;
            }
        __syncthreads();
        if (t == 0) {
            __threadfence();
            int old = atomicAdd(&g_ctr_h[jb], 1);
            slast = (old == KB6 - 1);
        }
        __syncthreads();
        if (!slast) return;
        __threadfence();
#pragma unroll
        for (int li = 0; li < 4; li++) {
            int flat = li * 256 + t;
            int b = flat >> 5, jq = flat & 31;
            float4 sum = *(const float4*)(bv1 + j0 + jq * 4);
#pragma unroll
            for (int p = 0; p < KB6; p++) {
                float4 v = __ldcg((const float4*)(g_hpart + ((size_t)p * 32 + b) * DD + j0 + jq * 4));
                sum.x += v.x; sum.y += v.y; sum.z += v.z; sum.w += v.w;
            }
            *(float4*)(g_hidden + (size_t)b * DD + j0 + jq * 4) = sum;
        }
        __threadfence();
        __syncthreads();
        if (t == 0) atomicAdd(&g_hready, 1);
        return;
    }

    // ---- k8a part ----
    float* Ws = cbuf;             // 256 x WSTR
    float* Hs = cbuf + 256 * WSTR;
    int idx = bid - 48;
    if (idx == 0 && t < BB) { g_sumtot[t] = 0.f; g_ctr_v[t] = 0; }
    int tv = t & 63, tb = t >> 6;
    int v0 = (idx % 192) * 256;
    int ks = idx / 192;
    int kbase = ks * 256;

    unsigned long long acc2[4][8];
#pragma unroll
    for (int j = 0; j < 4; j++)
#pragma unroll
        for (int bj = 0; bj < 8; bj++) acc2[j][bj] = 0ull;

    float4 wreg[4];
    float  hreg0, hreg1;
    {
        int k0 = kbase;
#pragma unroll
        for (int li = 0; li < 4; li++) {
            int flat = li * 256 + t;
            int v = flat >> 2, kq = flat & 3;
            int gv = v0 + v;
            wreg[li] = (gv < VV)
                ? *(const float4*)(Wv2 + (size_t)gv * DD + k0 + kq * 4)
                : make_float4(0.f, 0.f, 0.f, 0.f);
        }
#pragma unroll
        for (int li = 0; li < 4; li++) {
            int flat = li * 256 + t;
            int v = flat >> 2, kq = flat & 3;
            *(float4*)(Ws + v * WSTR + kq * 4) = wreg[li];
        }
    }
    // wait for hidden ready (W tile-0 staged already — DRAM overlap with k6)
    if (t == 0) {
        while (*(volatile int*)&g_hready < JB6) __nanosleep(64);
    }
    __syncthreads();
    __threadfence();
    {
        int k0 = kbase;
        hreg0 = __ldcg(&g_hidden[((t)       >> 4) * DD + k0 + ((t)       & 15)]);
        hreg1 = __ldcg(&g_hidden[((t + 256) >> 4) * DD + k0 + ((t + 256) & 15)]);
        Hs[t] = hreg0;
        Hs[t + 256] = hreg1;
    }
    __syncthreads();

    for (int tile = 0; tile < 16; tile++) {
        if (tile < 15) {
            int k0 = kbase + (tile + 1) * 16;
#pragma unroll
            for (int li = 0; li < 4; li++) {
                int flat = li * 256 + t;
                int v = flat >> 2, kq = flat & 3;
                int gv = v0 + v;
                wreg[li] = (gv < VV)
                    ? *(const float4*)(Wv2 + (size_t)gv * DD + k0 + kq * 4)
                    : make_float4(0.f, 0.f, 0.f, 0.f);
            }
            hreg0 = g_hidden[((t)       >> 4) * DD + k0 + ((t)       & 15)];
            hreg1 = g_hidden[((t + 256) >> 4) * DD + k0 + ((t + 256) & 15)];
        }
#pragma unroll
        for (int kq = 0; kq < 4; kq++) {
            ulonglong2 h2[8];
#pragma unroll
            for (int bj = 0; bj < 8; bj++)
                h2[bj] = *(const ulonglong2*)(Hs + (tb * 8 + bj) * 16 + kq * 4);
#pragma unroll
            for (int j = 0; j < 4; j++) {
                ulonglong2 w2 = *(const ulonglong2*)(Ws + (tv + 64 * j) * WSTR + kq * 4);
#pragma unroll
                for (int bj = 0; bj < 8; bj++) {
                    asm("fma.rn.f32x2 %0, %1, %2, %0;"
                        : "+l"(acc2[j][bj]) : "l"(w2.x), "l"(h2[bj].x));
                    asm("fma.rn.f32x2 %0, %1, %2, %0;"
                        : "+l"(acc2[j][bj]) : "l"(w2.y), "l"(h2[bj].y));
                }
            }
        }
        if (tile < 15) {
            __syncthreads();
#pragma unroll
            for (int li = 0; li < 4; li++) {
                int flat = li * 256 + t;
                int v = flat >> 2, kq = flat & 3;
                *(float4*)(Ws + v * WSTR + kq * 4) = wreg[li];
            }
            Hs[t] = hreg0;
            Hs[t + 256] = hreg1;
            __syncthreads();
        }
    }
    float accf[4][8];
#pragma unroll
    for (int j = 0; j < 4; j++)
#pragma unroll
        for (int bj = 0; bj < 8; bj++) {
            unsigned long long a = acc2[j][bj];
            accf[j][bj] = __uint_as_float((unsigned)(a & 0xffffffffu)) +
                          __uint_as_float((unsigned)(a >> 32));
        }
#pragma unroll
    for (int p = 0; p < 2; p++) {
        __syncthreads();
        if ((tb >> 1) == p) {
#pragma unroll
            for (int j = 0; j < 4; j++)
#pragma unroll
                for (int bj = 0; bj < 8; bj++)
                    Ws[((tb & 1) * 8 + bj) * 256 + tv + 64 * j] = accf[j][bj];
        }
        __syncthreads();
#pragma unroll
        for (int i = 0; i < 4; i++) {
            int ii = i * 256 + t;
            int row = ii >> 6, col = ii & 63;
            *(float4*)(g_lpart + ((size_t)(ks * 32 + p * 16 + row) * VP + v0 + col * 4)) =
                *(const float4*)(Ws + row * 256 + col * 4);
        }
    }
}

// ===========================================================================
// D: k8b exp + per-b sum + last-block tail: scatter + row scale + zero-fix
// ===========================================================================
__global__ void kD_exp_final(const float* __restrict__ bv2, float* __restrict__ dout,
                             const int* __restrict__ src) {
    int b = blockIdx.x, cb = blockIdx.y, t = threadIdx.x;
    int base = cb * 2048;
    float sum = 0.f;
#pragma unroll
    for (int it = 0; it < 8; it++) {
        int v = base + it * 256 + t;
        if (v < VV) {
            float l = g_lpart[(size_t)b * VP + v] + g_lpart[(size_t)(32 + b) * VP + v] + bv2[v];
            float e = __expf(l);
            dout[(size_t)b * VF + v] = e;
            sum += e;
        } else if (v < VF) {
            dout[(size_t)b * VF + v] = 0.f;
        }
    }
    __shared__ float sm[8];
    __shared__ int slast;
#pragma unroll
    for (int o = 16; o; o >>= 1) sum += __shfl_down_sync(0xffffffffu, sum, o);
    if (!(t & 31)) sm[t >> 5] = sum;
    __syncthreads();
    if (t == 0) {
        float tot = 0.f;
#pragma unroll
        for (int i = 0; i < 8; i++) tot += sm[i];
        atomicAdd(&g_sumtot[b], tot);
        __threadfence();
        int old = atomicAdd(&g_ctr_v[b], 1);
        slast = (old == NCB - 1);
    }
    __syncthreads();
    if (!slast) return;
    __threadfence();
    float s = __ldcg(&g_sumtot[b]);
    float pg = g_pgen[b];
    float f = (1.f - pg) * s / pg;   // pre-scaled; final pass multiplies by pg/s
#pragma unroll
    for (int it = 0; it < 4; it++) {
        int si = it * 256 + t;
        int idx = src[b * SS + si];
        float val = f * g_attn[b * SS + si];
        atomicAdd(dout + (size_t)b * VF + idx, val);
    }
    __threadfence();
    __syncthreads();
    // scale + zero-fix the whole row b (12500 float4s over 256 threads)
    float sc = pg / s;
    float4* rowp = (float4*)(dout + (size_t)b * VF);
    for (int i = t; i < VF / 4; i += 256) {
        float4 v = __ldcg(rowp + i);
        v.x *= sc; if (v.x == 0.f) v.x = 1e-12f;
        v.y *= sc; if (v.y == 0.f) v.y = 1e-12f;
        v.z *= sc; if (v.z == 0.f) v.z = 1e-12f;
        v.w *= sc; if (v.w == 0.f) v.w = 1e-12f;
        rowp[i] = v;
    }
}

extern "C" void kernel_launch(void* const* d_in, const int* in_sizes, int n_in,
                              void* d_out, int out_size) {
    const float* dec_output = (const float*)d_in[0];
    const float* hh         = (const float*)d_in[1];
    const float* cc         = (const float*)d_in[2];
    const float* dinp       = (const float*)d_in[3];
    const float* enc        = (const float*)d_in[4];
    const float* enc1       = (const float*)d_in[5];
    const int*   src        = (const int*)  d_in[6];
    const float* W_dec      = (const float*)d_in[7];
    const float* b_dec      = (const float*)d_in[8];
    const float* w_attn     = (const float*)d_in[9];
    const float* W_v1       = (const float*)d_in[10];
    const float* b_v1       = (const float*)d_in[11];
    const float* W_v2       = (const float*)d_in[12];
    const float* b_v2       = (const float*)d_in[13];
    const float* W_p        = (const float*)d_in[14];
    const float* b_p        = (const float*)d_in[15];
    const float* gam        = (const float*)d_in[16];
    const float* bet        = (const float*)d_in[17];
    const float* bn_m       = (const float*)d_in[18];
    const float* bn_v       = (const float*)d_in[19];

    float* dout     = (float*)d_out;
    float* out_attn = dout + BB * VF;
    float* out_ctx  = out_attn + BB * SS;

    kA_dec1_scores<<<4224, 256>>>(hh, cc, dec_output, W_dec, b_dec,
                                  (const float4*)enc1, (const float4*)w_attn);
    kB_ctx        <<<dim3(NSC, 32), 256>>>((const float4*)enc, src, out_attn,
                                           bn_m, bn_v, gam, bet, W_p, b_p,
                                           hh, cc, dinp, out_ctx);
    kC_hidden_logits<<<432, 256>>>(W_v1, b_v1, W_v2);
    kD_exp_final  <<<dim3(32, NCB), 256>>>(b_v2, dout, src);
}

// round 8
// speedup vs baseline: 1.4164x; 1.0219x over previous
#include <cuda_runtime.h>

#define BB   32
#define SS   1024
#define DD   512
#define D2   1024
#define D3   1536
#define VV   49000
#define VP   49152
#define VF   50000
#define NCB  25
#define NSC  16
#define KB6  12
#define JB6  4

__device__ __align__(16) float g_temp_t [D3 * BB];
__device__ __align__(16) float g_dec1   [BB * D2];
__device__ __align__(16) float g_scores [BB * SS];
__device__ __align__(16) float g_attn   [BB * SS];
__device__ __align__(16) float g_ctxpart[NSC * BB * D2];
__device__ __align__(16) float g_hpart  [KB6 * BB * DD];
__device__ __align__(16) float g_hidden [BB * DD];
__device__            float g_pgen  [BB];
__device__ __align__(16) float g_lpart [2 * BB * VP];
__device__            float g_sumtot[BB];
__device__            int   g_ctr_dec1;
__device__            int   g_ctr_ctx[BB];
__device__            int   g_ctr_v  [BB];
__device__            int   g_ctr_h  [JB6];
__device__            int   g_hready;
__device__            int   g_scat  [BB];

__device__ __forceinline__ float fast_tanh(float x) {
    float y;
    asm("tanh.approx.f32 %0, %1;" : "=f"(y) : "f"(x));
    return y;
}

// ===========================================================================
// A: fused k1f (dec1 GEMV, bids 0..127) + k2 (scores, bids 128..4223)
// ===========================================================================
__global__ void kA_dec1_scores(const float* __restrict__ h, const float* __restrict__ c,
                               const float* __restrict__ dec_output,
                               const float* __restrict__ W, const float* __restrict__ bias,
                               const float4* __restrict__ enc1,
                               const float4* __restrict__ wattn) {
    __shared__ __align__(16) float abuf[5152];
    int t = threadIdx.x;
    int bid = blockIdx.x;

    if (bid < 128) {
        if (bid == 0 && t < BB) g_ctr_ctx[t] = 0;
        float* sdec = abuf;            // [32][129]
        float* sW   = abuf + 4128;     // [8][128]
        int jj = t >> 5, b = t & 31;
        int j0 = bid * 8;
        if (t < 128) {
            int i = bid * 128 + t;
            int k = i >> 5, bb = i & 31;
            g_temp_t[i] = dec_output[bb * DD + k];
        }
        float a0 = 0.f, a1 = 0.f, a2 = 0.f, a3 = 0.f;
        for (int ch = 0; ch < 8; ch++) {
            int k0 = ch * 128;
            __syncthreads();
#pragma unroll
            for (int m = 0; m < 16; m++) {
                int e = m * 256 + t;
                int bb = e >> 7, kk = e & 127;
                int kg = k0 + kk;
                sdec[bb * 129 + kk] = (kg < DD) ? h[bb * DD + kg] : c[bb * DD + kg - DD];
            }
#pragma unroll
            for (int m = 0; m < 4; m++) {
                int e = m * 256 + t;
                int jx = e >> 7, kk = e & 127;
                sW[jx * 128 + kk] = W[(j0 + jx) * D2 + k0 + kk];
            }
            __syncthreads();
#pragma unroll
            for (int kk = 0; kk < 128; kk += 4) {
                a0 += sW[jj * 128 + kk + 0] * sdec[b * 129 + kk + 0];
                a1 += sW[jj * 128 + kk + 1] * sdec[b * 129 + kk + 1];
                a2 += sW[jj * 128 + kk + 2] * sdec[b * 129 + kk + 2];
                a3 += sW[jj * 128 + kk + 3] * sdec[b * 129 + kk + 3];
            }
        }
        g_dec1[b * D2 + j0 + jj] = (a0 + a1) + (a2 + a3) + bias[j0 + jj];
        __threadfence();
        __syncthreads();
        if (t == 0) atomicAdd(&g_ctr_dec1, 1);
        return;
    }

    // ---- k2 part ----
    float4* sd1 = (float4*)abuf;          // [256]
    float4* swa = ((float4*)abuf) + 256;  // [256]
    int row0 = (bid - 128) * 8;
    int b = row0 >> 10;
    swa[t] = wattn[t];
    int lane = t & 31, w = t >> 5;
    int row = row0 + w;
    float4 e[8];
#pragma unroll
    for (int i = 0; i < 8; i++)
        e[i] = enc1[(size_t)row * 256 + i * 32 + lane];
    if (t == 0) {
        while (*(volatile int*)&g_ctr_dec1 < 128) __nanosleep(64);
    }
    __syncthreads();
    __threadfence();
    sd1[t] = __ldcg(((const float4*)g_dec1) + b * 256 + t);
    __syncthreads();
    float acc = 0.f;
#pragma unroll
    for (int i = 0; i < 8; i++) {
        int cidx = i * 32 + lane;
        float4 dd = sd1[cidx];
        float4 wa = swa[cidx];
        acc += fast_tanh(e[i].x + dd.x) * wa.x;
        acc += fast_tanh(e[i].y + dd.y) * wa.y;
        acc += fast_tanh(e[i].z + dd.z) * wa.z;
        acc += fast_tanh(e[i].w + dd.w) * wa.w;
    }
#pragma unroll
    for (int o = 16; o; o >>= 1) acc += __shfl_down_sync(0xffffffffu, acc, o);
    if (!lane) g_scores[row] = acc;
}

// ===========================================================================
// B: softmax + context partial + last-block tail (BN + ctx + p_gen)
// ===========================================================================
__global__ void kB_ctx(const float4* __restrict__ enc, const int* __restrict__ src,
                       float* __restrict__ out_attn,
                       const float* __restrict__ bn_m, const float* __restrict__ bn_v,
                       const float* __restrict__ gam,  const float* __restrict__ bet,
                       const float* __restrict__ Wp,   const float* __restrict__ bp,
                       const float* __restrict__ hh,   const float* __restrict__ cc,
                       const float* __restrict__ dinp, float* __restrict__ out_ctx) {
    int sc = blockIdx.x, b = blockIdx.y, t = threadIdx.x;
    __shared__ float satt[1024];
    __shared__ float sm[8];
    __shared__ float bc;
    __shared__ int slast;
    if (sc == 0 && b == 0) {
        if (t == 0) { g_ctr_dec1 = 0; g_hready = 0; }
        if (t < JB6) g_ctr_h[t] = 0;
    }
    float4 s = ((const float4*)g_scores)[b * 256 + t];
    float m = fmaxf(fmaxf(s.x, s.y), fmaxf(s.z, s.w));
#pragma unroll
    for (int o = 16; o; o >>= 1) m = fmaxf(m, __shfl_down_sync(0xffffffffu, m, o));
    if (!(t & 31)) sm[t >> 5] = m;
    __syncthreads();
    if (t == 0) {
        float mm = sm[0];
#pragma unroll
        for (int i = 1; i < 8; i++) mm = fmaxf(mm, sm[i]);
        bc = mm;
    }
    __syncthreads();
    float mx = bc;
    __syncthreads();
    int4 id = ((const int4*)src)[b * 256 + t];
    float4 e;
    e.x = (id.x != 0) ? __expf(s.x - mx) : 0.f;
    e.y = (id.y != 0) ? __expf(s.y - mx) : 0.f;
    e.z = (id.z != 0) ? __expf(s.z - mx) : 0.f;
    e.w = (id.w != 0) ? __expf(s.w - mx) : 0.f;
    float sum = e.x + e.y + e.z + e.w;
#pragma unroll
    for (int o = 16; o; o >>= 1) sum += __shfl_down_sync(0xffffffffu, sum, o);
    if (!(t & 31)) sm[t >> 5] = sum;
    __syncthreads();
    if (t == 0) {
        float tt = 0.f;
#pragma unroll
        for (int i = 0; i < 8; i++) tt += sm[i];
        bc = 1.f / tt;
    }
    __syncthreads();
    float inv = bc;
    float4 a = make_float4(e.x * inv, e.y * inv, e.z * inv, e.w * inv);
    ((float4*)satt)[t] = a;
    __syncthreads();
    if (sc == 0) {
        ((float4*)g_attn)[b * 256 + t] = a;
        ((float4*)out_attn)[b * 256 + t] = a;
    }
    int s0 = sc * (SS / NSC);
    float4 acc = make_float4(0.f, 0.f, 0.f, 0.f);
    const float4* base = enc + (size_t)(b * SS + s0) * 256 + t;
#pragma unroll 8
    for (int ss = 0; ss < SS / NSC; ss++) {
        float  aa = satt[s0 + ss];
        float4 ee = base[(size_t)ss * 256];
        acc.x += aa * ee.x; acc.y += aa * ee.y; acc.z += aa * ee.z; acc.w += aa * ee.w;
    }
    ((float4*)g_ctxpart)[(sc * 32 + b) * 256 + t] = acc;
    __syncthreads();
    if (t == 0) {
        __threadfence();
        int old = atomicAdd(&g_ctr_ctx[b], 1);
        slast = (old == NSC - 1);
    }
    __syncthreads();
    if (!slast) return;
    __threadfence();
    float sv[4] = {0.f, 0.f, 0.f, 0.f};
#pragma unroll
    for (int scc = 0; scc < NSC; scc++) {
        float4 p = __ldcg(((const float4*)g_ctxpart) + (scc * 32 + b) * 256 + t);
        sv[0] += p.x; sv[1] += p.y; sv[2] += p.z; sv[3] += p.w;
    }
    int d = 4 * t;
    float ctx[4];
    float pp = 0.f;
#pragma unroll
    for (int i = 0; i < 4; i++) {
        int dd = d + i;
        float cx = (sv[i] - bn_m[dd]) * rsqrtf(bn_v[dd] + 1e-5f) * gam[dd] + bet[dd];
        ctx[i] = cx;
        g_temp_t[(DD + dd) * 32 + b] = cx;
        float dop = (dd < DD) ? hh[b * DD + dd] : cc[b * DD + dd - DD];
        pp += Wp[dd] * cx + Wp[D2 + dd] * dop;
    }
    ((float4*)out_ctx)[b * 256 + t] = make_float4(ctx[0], ctx[1], ctx[2], ctx[3]);
    if (t < 128) {
#pragma unroll
        for (int i = 0; i < 4; i++) {
            int dd = 4 * t + i;
            pp += Wp[2048 + dd] * dinp[b * DD + dd];
        }
    }
#pragma unroll
    for (int o = 16; o; o >>= 1) pp += __shfl_down_sync(0xffffffffu, pp, o);
    if (!(t & 31)) sm[t >> 5] = pp;
    __syncthreads();
    if (t == 0) {
        float tot = bp[0];
#pragma unroll
        for (int i = 0; i < 8; i++) tot += sm[i];
        g_pgen[b] = 1.f / (1.f + __expf(-tot));
    }
}

// ===========================================================================
// C: fused k6 (hidden GEMM, bids 0..47) + k8a (vocab logits, bids 48..431)
// ===========================================================================
#define XS6  68
#define WSTR 20
__global__ void __launch_bounds__(256, 2)
kC_hidden_logits(const float* __restrict__ Wv1, const float* __restrict__ bv1,
                 const float* __restrict__ Wv2) {
    __shared__ __align__(16) float cbuf[10880];
    __shared__ int slast;
    int t = threadIdx.x;
    int bid = blockIdx.x;

    if (bid < 48) {
        float* sW = cbuf;
        float* sX = cbuf + 128 * XS6;
        int tj = t & 63, tb = t >> 6;
        int jb = bid & 3, kb = bid >> 2;
        int j0 = jb * 128;
        unsigned long long acc2[2][8];
#pragma unroll
        for (int jr = 0; jr < 2; jr++)
#pragma unroll
            for (int bj = 0; bj < 8; bj++) acc2[jr][bj] = 0ull;
#pragma unroll
        for (int sub = 0; sub < 2; sub++) {
            int k0s = kb * 128 + sub * 64;
            __syncthreads();
#pragma unroll
            for (int li = 0; li < 8; li++) {
                int flat = li * 256 + t;
                int row = flat >> 4, kc = flat & 15;
                float4 f = *(const float4*)(Wv1 + (size_t)(j0 + row) * D3 + k0s + kc * 4);
                *(float4*)(sW + row * XS6 + kc * 4) = f;
            }
#pragma unroll
            for (int li = 0; li < 2; li++) {
                int flat = li * 256 + t;
                int kk = flat >> 3, bq = flat & 7;
                float4 f = ((const float4*)g_temp_t)[(size_t)(k0s + kk) * 8 + bq];
                sX[(bq * 4 + 0) * XS6 + kk] = f.x;
                sX[(bq * 4 + 1) * XS6 + kk] = f.y;
                sX[(bq * 4 + 2) * XS6 + kk] = f.z;
                sX[(bq * 4 + 3) * XS6 + kk] = f.w;
            }
            __syncthreads();
#pragma unroll
            for (int kq = 0; kq < 16; kq++) {
                ulonglong2 xv[8];
#pragma unroll
                for (int bj = 0; bj < 8; bj++)
                    xv[bj] = *(const ulonglong2*)(sX + (tb * 8 + bj) * XS6 + kq * 4);
#pragma unroll
                for (int jr = 0; jr < 2; jr++) {
                    ulonglong2 wv = *(const ulonglong2*)(sW + (jr * 64 + tj) * XS6 + kq * 4);
#pragma unroll
                    for (int bj = 0; bj < 8; bj++) {
                        asm("fma.rn.f32x2 %0, %1, %2, %0;"
                            : "+l"(acc2[jr][bj]) : "l"(wv.x), "l"(xv[bj].x));
                        asm("fma.rn.f32x2 %0, %1, %2, %0;"
                            : "+l"(acc2[jr][bj]) : "l"(wv.y), "l"(xv[bj].y));
                    }
                }
            }
        }
#pragma unroll
        for (int jr = 0; jr < 2; jr++)
#pragma unroll
            for (int bj = 0; bj < 8; bj++) {
                unsigned long long a = acc2[jr][bj];
                float v = __uint_as_float((unsigned)(a & 0xffffffffu)) +
                          __uint_as_float((unsigned)(a >> 32));
                g_hpart[((size_t)kb * 32 + tb * 8 + bj) * DD + j0 + jr * 64 + tj] = v;
            }
        __syncthreads();
        if (t == 0) {
            __threadfence();
            int old = atomicAdd(&g_ctr_h[jb], 1);
            slast = (old == KB6 - 1);
        }
        __syncthreads();
        if (!slast) return;
        __threadfence();
#pragma unroll
        for (int li = 0; li < 4; li++) {
            int flat = li * 256 + t;
            int b = flat >> 5, jq = flat & 31;
            float4 sum = *(const float4*)(bv1 + j0 + jq * 4);
#pragma unroll
            for (int p = 0; p < KB6; p++) {
                float4 v = __ldcg((const float4*)(g_hpart + ((size_t)p * 32 + b) * DD + j0 + jq * 4));
                sum.x += v.x; sum.y += v.y; sum.z += v.z; sum.w += v.w;
            }
            *(float4*)(g_hidden + (size_t)b * DD + j0 + jq * 4) = sum;
        }
        __threadfence();
        __syncthreads();
        if (t == 0) atomicAdd(&g_hready, 1);
        return;
    }

    // ---- k8a part ----
    float* Ws = cbuf;
    float* Hs = cbuf + 256 * WSTR;
    int idx = bid - 48;
    if (idx == 0 && t < BB) { g_sumtot[t] = 0.f; g_ctr_v[t] = 0; g_scat[t] = 0; }
    int tv = t & 63, tb = t >> 6;
    int v0 = (idx % 192) * 256;
    int ks = idx / 192;
    int kbase = ks * 256;

    unsigned long long acc2[4][8];
#pragma unroll
    for (int j = 0; j < 4; j++)
#pragma unroll
        for (int bj = 0; bj < 8; bj++) acc2[j][bj] = 0ull;

    float4 wreg[4];
    float  hreg0, hreg1;
    {
        int k0 = kbase;
#pragma unroll
        for (int li = 0; li < 4; li++) {
            int flat = li * 256 + t;
            int v = flat >> 2, kq = flat & 3;
            int gv = v0 + v;
            wreg[li] = (gv < VV)
                ? *(const float4*)(Wv2 + (size_t)gv * DD + k0 + kq * 4)
                : make_float4(0.f, 0.f, 0.f, 0.f);
        }
#pragma unroll
        for (int li = 0; li < 4; li++) {
            int flat = li * 256 + t;
            int v = flat >> 2, kq = flat & 3;
            *(float4*)(Ws + v * WSTR + kq * 4) = wreg[li];
        }
    }
    if (t == 0) {
        while (*(volatile int*)&g_hready < JB6) __nanosleep(64);
    }
    __syncthreads();
    __threadfence();
    {
        int k0 = kbase;
        hreg0 = __ldcg(&g_hidden[((t)       >> 4) * DD + k0 + ((t)       & 15)]);
        hreg1 = __ldcg(&g_hidden[((t + 256) >> 4) * DD + k0 + ((t + 256) & 15)]);
        Hs[t] = hreg0;
        Hs[t + 256] = hreg1;
    }
    __syncthreads();

    for (int tile = 0; tile < 16; tile++) {
        if (tile < 15) {
            int k0 = kbase + (tile + 1) * 16;
#pragma unroll
            for (int li = 0; li < 4; li++) {
                int flat = li * 256 + t;
                int v = flat >> 2, kq = flat & 3;
                int gv = v0 + v;
                wreg[li] = (gv < VV)
                    ? *(const float4*)(Wv2 + (size_t)gv * DD + k0 + kq * 4)
                    : make_float4(0.f, 0.f, 0.f, 0.f);
            }
            hreg0 = g_hidden[((t)       >> 4) * DD + k0 + ((t)       & 15)];
            hreg1 = g_hidden[((t + 256) >> 4) * DD + k0 + ((t + 256) & 15)];
        }
#pragma unroll
        for (int kq = 0; kq < 4; kq++) {
            ulonglong2 h2[8];
#pragma unroll
            for (int bj = 0; bj < 8; bj++)
                h2[bj] = *(const ulonglong2*)(Hs + (tb * 8 + bj) * 16 + kq * 4);
#pragma unroll
            for (int j = 0; j < 4; j++) {
                ulonglong2 w2 = *(const ulonglong2*)(Ws + (tv + 64 * j) * WSTR + kq * 4);
#pragma unroll
                for (int bj = 0; bj < 8; bj++) {
                    asm("fma.rn.f32x2 %0, %1, %2, %0;"
                        : "+l"(acc2[j][bj]) : "l"(w2.x), "l"(h2[bj].x));
                    asm("fma.rn.f32x2 %0, %1, %2, %0;"
                        : "+l"(acc2[j][bj]) : "l"(w2.y), "l"(h2[bj].y));
                }
            }
        }
        if (tile < 15) {
            __syncthreads();
#pragma unroll
            for (int li = 0; li < 4; li++) {
                int flat = li * 256 + t;
                int v = flat >> 2, kq = flat & 3;
                *(float4*)(Ws + v * WSTR + kq * 4) = wreg[li];
            }
            Hs[t] = hreg0;
            Hs[t + 256] = hreg1;
            __syncthreads();
        }
    }
    float accf[4][8];
#pragma unroll
    for (int j = 0; j < 4; j++)
#pragma unroll
        for (int bj = 0; bj < 8; bj++) {
            unsigned long long a = acc2[j][bj];
            accf[j][bj] = __uint_as_float((unsigned)(a & 0xffffffffu)) +
                          __uint_as_float((unsigned)(a >> 32));
        }
#pragma unroll
    for (int p = 0; p < 2; p++) {
        __syncthreads();
        if ((tb >> 1) == p) {
#pragma unroll
            for (int j = 0; j < 4; j++)
#pragma unroll
                for (int bj = 0; bj < 8; bj++)
                    Ws[((tb & 1) * 8 + bj) * 256 + tv + 64 * j] = accf[j][bj];
        }
        __syncthreads();
#pragma unroll
        for (int i = 0; i < 4; i++) {
            int ii = i * 256 + t;
            int row = ii >> 6, col = ii & 63;
            *(float4*)(g_lpart + ((size_t)(ks * 32 + p * 16 + row) * VP + v0 + col * 4)) =
                *(const float4*)(Ws + row * 256 + col * 4);
        }
    }
}

// ===========================================================================
// D: exp + sum; last block scatters (pre-scaled) + sets flag; ALL blocks then
//    scale + zero-fix their own 2048-col chunk (tail parallel over 800 blocks)
// ===========================================================================
__global__ void kD_exp_final(const float* __restrict__ bv2, float* __restrict__ dout,
                             const int* __restrict__ src) {
    int b = blockIdx.x, cb = blockIdx.y, t = threadIdx.x;
    int base = cb * 2048;
    float sum = 0.f;
#pragma unroll
    for (int it = 0; it < 8; it++) {
        int v = base + it * 256 + t;
        if (v < VV) {
            float l = g_lpart[(size_t)b * VP + v] + g_lpart[(size_t)(32 + b) * VP + v] + bv2[v];
            float e = __expf(l);
            dout[(size_t)b * VF + v] = e;
            sum += e;
        } else if (v < VF) {
            dout[(size_t)b * VF + v] = 0.f;
        }
    }
    __shared__ float sm[8];
    __shared__ int slast;
#pragma unroll
    for (int o = 16; o; o >>= 1) sum += __shfl_down_sync(0xffffffffu, sum, o);
    if (!(t & 31)) sm[t >> 5] = sum;
    __syncthreads();
    if (t == 0) {
        float tot = 0.f;
#pragma unroll
        for (int i = 0; i < 8; i++) tot += sm[i];
        atomicAdd(&g_sumtot[b], tot);
        __threadfence();
        int old = atomicAdd(&g_ctr_v[b], 1);
        slast = (old == NCB - 1);
    }
    __syncthreads();
    if (slast) {
        __threadfence();
        float s = __ldcg(&g_sumtot[b]);
        float pg = g_pgen[b];
        float f = (1.f - pg) * s / pg;   // pre-scaled; uniform scale below lands both
#pragma unroll
        for (int it = 0; it < 4; it++) {
            int si = it * 256 + t;
            int idx = src[b * SS + si];
            float val = f * g_attn[b * SS + si];
            atomicAdd(dout + (size_t)b * VF + idx, val);
        }
        __threadfence();
        __syncthreads();
        if (t == 0) atomicExch(&g_scat[b], 1);
    }
    // all blocks of row b wait for scatter, then scale own chunk
    if (t == 0) {
        while (*(volatile int*)&g_scat[b] == 0) __nanosleep(32);
    }
    __syncthreads();
    __threadfence();
    float s = __ldcg(&g_sumtot[b]);
    float sc = g_pgen[b] / s;
#pragma unroll
    for (int it = 0; it < 8; it++) {
        int v = base + it * 256 + t;
        if (v < VF) {
            float p = __ldcg(&dout[(size_t)b * VF + v]) * sc;
            if (p == 0.f) p = 1e-12f;
            dout[(size_t)b * VF + v] = p;
        }
    }
}

extern "C" void kernel_launch(void* const* d_in, const int* in_sizes, int n_in,
                              void* d_out, int out_size) {
    const float* dec_output = (const float*)d_in[0];
    const float* hh         = (const float*)d_in[1];
    const float* cc         = (const float*)d_in[2];
    const float* dinp       = (const float*)d_in[3];
    const float* enc        = (const float*)d_in[4];
    const float* enc1       = (const float*)d_in[5];
    const int*   src        = (const int*)  d_in[6];
    const float* W_dec      = (const float*)d_in[7];
    const float* b_dec      = (const float*)d_in[8];
    const float* w_attn     = (const float*)d_in[9];
    const float* W_v1       = (const float*)d_in[10];
    const float* b_v1       = (const float*)d_in[11];
    const float* W_v2       = (const float*)d_in[12];
    const float* b_v2       = (const float*)d_in[13];
    const float* W_p        = (const float*)d_in[14];
    const float* b_p        = (const float*)d_in[15];
    const float* gam        = (const float*)d_in[16];
    const float* bet        = (const float*)d_in[17];
    const float* bn_m       = (const float*)d_in[18];
    const float* bn_v       = (const float*)d_in[19];

    float* dout     = (float*)d_out;
    float* out_attn = dout + BB * VF;
    float* out_ctx  = out_attn + BB * SS;

    kA_dec1_scores<<<4224, 256>>>(hh, cc, dec_output, W_dec, b_dec,
                                  (const float4*)enc1, (const float4*)w_attn);
    kB_ctx        <<<dim3(NSC, 32), 256>>>((const float4*)enc, src, out_attn,
                                           bn_m, bn_v, gam, bet, W_p, b_p,
                                           hh, cc, dinp, out_ctx);
    kC_hidden_logits<<<432, 256>>>(W_v1, b_v1, W_v2);
    kD_exp_final  <<<dim3(32, NCB), 256>>>(b_v2, dout, src);
}

// round 9
// speedup vs baseline: 1.4729x; 1.0399x over previous
#include <cuda_runtime.h>

#define BB   32
#define SS   1024
#define DD   512
#define D2   1024
#define D3   1536
#define VV   49000
#define VP   49152
#define VF   50000
#define NCB  25
#define NSC  16
#define KB6  12
#define JB6  4

__device__ __align__(16) float g_temp_t [D3 * BB];
__device__ __align__(16) float g_dec1   [BB * D2];
__device__ __align__(16) float g_scores [BB * SS];
__device__ __align__(16) float g_attn   [BB * SS];
__device__ __align__(16) float g_ctxpart[NSC * BB * D2];
__device__ __align__(16) float g_hpart  [KB6 * BB * DD];
__device__ __align__(16) float g_hidden [BB * DD];
__device__            float g_pgen  [BB];
__device__ __align__(16) float g_lpart [2 * BB * VP];
__device__            float g_sumtot[BB];
__device__            int   g_ctr_dec1;
__device__            int   g_ctr_s  [BB];
__device__            int   g_ctr_ctx[BB];
__device__            int   g_ctr_v  [BB];
__device__            int   g_ctr_h  [JB6];
__device__            int   g_hready;

__device__ __forceinline__ float fast_tanh(float x) {
    float y;
    asm("tanh.approx.f32 %0, %1;" : "=f"(y) : "f"(x));
    return y;
}

// ===========================================================================
// A: dec1 GEMV (bids 0..127) + scores (128..4223) + softmax/ctx/BN/pgen (4224..4735)
// ===========================================================================
__global__ void kA_all(const float* __restrict__ h, const float* __restrict__ c,
                       const float* __restrict__ dec_output,
                       const float* __restrict__ W, const float* __restrict__ bias,
                       const float4* __restrict__ enc1, const float4* __restrict__ wattn,
                       const float4* __restrict__ enc, const int* __restrict__ src,
                       float* __restrict__ out_attn,
                       const float* __restrict__ bn_m, const float* __restrict__ bn_v,
                       const float* __restrict__ gam,  const float* __restrict__ bet,
                       const float* __restrict__ Wp,   const float* __restrict__ bp,
                       const float* __restrict__ dinp, float* __restrict__ out_ctx) {
    __shared__ __align__(16) float abuf[5152];
    __shared__ float sm[8];
    __shared__ float bc;
    __shared__ int slast;
    int t = threadIdx.x;
    int bid = blockIdx.x;

    if (bid < 128) {
        // ---- dec1 GEMV ----
        float* sdec = abuf;            // [32][129]
        float* sW   = abuf + 4128;     // [8][128]
        int jj = t >> 5, b = t & 31;
        int j0 = bid * 8;
        if (t < 128) {
            int i = bid * 128 + t;
            int k = i >> 5, bb = i & 31;
            g_temp_t[i] = dec_output[bb * DD + k];
        }
        float a0 = 0.f, a1 = 0.f, a2 = 0.f, a3 = 0.f;
        for (int ch = 0; ch < 8; ch++) {
            int k0 = ch * 128;
            __syncthreads();
#pragma unroll
            for (int m = 0; m < 16; m++) {
                int e = m * 256 + t;
                int bb = e >> 7, kk = e & 127;
                int kg = k0 + kk;
                sdec[bb * 129 + kk] = (kg < DD) ? h[bb * DD + kg] : c[bb * DD + kg - DD];
            }
#pragma unroll
            for (int m = 0; m < 4; m++) {
                int e = m * 256 + t;
                int jx = e >> 7, kk = e & 127;
                sW[jx * 128 + kk] = W[(j0 + jx) * D2 + k0 + kk];
            }
            __syncthreads();
#pragma unroll
            for (int kk = 0; kk < 128; kk += 4) {
                a0 += sW[jj * 128 + kk + 0] * sdec[b * 129 + kk + 0];
                a1 += sW[jj * 128 + kk + 1] * sdec[b * 129 + kk + 1];
                a2 += sW[jj * 128 + kk + 2] * sdec[b * 129 + kk + 2];
                a3 += sW[jj * 128 + kk + 3] * sdec[b * 129 + kk + 3];
            }
        }
        g_dec1[b * D2 + j0 + jj] = (a0 + a1) + (a2 + a3) + bias[j0 + jj];
        __threadfence();
        __syncthreads();
        if (t == 0) atomicAdd(&g_ctr_dec1, 1);
        return;
    }

    if (bid < 4224) {
        // ---- scores ----
        float4* sd1 = (float4*)abuf;          // [256]
        float4* swa = ((float4*)abuf) + 256;  // [256]
        int row0 = (bid - 128) * 8;
        int b = row0 >> 10;
        swa[t] = wattn[t];
        int lane = t & 31, w = t >> 5;
        int row = row0 + w;
        float4 e[8];
#pragma unroll
        for (int i = 0; i < 8; i++)
            e[i] = enc1[(size_t)row * 256 + i * 32 + lane];
        if (t == 0) {
            while (*(volatile int*)&g_ctr_dec1 < 128) __nanosleep(64);
        }
        __syncthreads();
        __threadfence();
        sd1[t] = __ldcg(((const float4*)g_dec1) + b * 256 + t);
        __syncthreads();
        float acc = 0.f;
#pragma unroll
        for (int i = 0; i < 8; i++) {
            int cidx = i * 32 + lane;
            float4 dd = sd1[cidx];
            float4 wa = swa[cidx];
            acc += fast_tanh(e[i].x + dd.x) * wa.x;
            acc += fast_tanh(e[i].y + dd.y) * wa.y;
            acc += fast_tanh(e[i].z + dd.z) * wa.z;
            acc += fast_tanh(e[i].w + dd.w) * wa.w;
        }
#pragma unroll
        for (int o = 16; o; o >>= 1) acc += __shfl_down_sync(0xffffffffu, acc, o);
        if (!lane) g_scores[row] = acc;
        __threadfence();
        __syncthreads();
        if (t == 0) atomicAdd(&g_ctr_s[b], 1);
        return;
    }

    // ---- softmax + context partial + last-block tail ----
    int idx = bid - 4224;
    int b = idx & 31, sc = idx >> 5;
    float* satt = abuf;   // [1024]
    if (t == 0) {
        while (*(volatile int*)&g_ctr_s[b] < 128) __nanosleep(64);
    }
    __syncthreads();
    __threadfence();
    float4 s = __ldcg(((const float4*)g_scores) + b * 256 + t);
    float m = fmaxf(fmaxf(s.x, s.y), fmaxf(s.z, s.w));
#pragma unroll
    for (int o = 16; o; o >>= 1) m = fmaxf(m, __shfl_down_sync(0xffffffffu, m, o));
    if (!(t & 31)) sm[t >> 5] = m;
    __syncthreads();
    if (t == 0) {
        float mm = sm[0];
#pragma unroll
        for (int i = 1; i < 8; i++) mm = fmaxf(mm, sm[i]);
        bc = mm;
    }
    __syncthreads();
    float mx = bc;
    __syncthreads();
    int4 id = ((const int4*)src)[b * 256 + t];
    float4 e;
    e.x = (id.x != 0) ? __expf(s.x - mx) : 0.f;
    e.y = (id.y != 0) ? __expf(s.y - mx) : 0.f;
    e.z = (id.z != 0) ? __expf(s.z - mx) : 0.f;
    e.w = (id.w != 0) ? __expf(s.w - mx) : 0.f;
    float sum = e.x + e.y + e.z + e.w;
#pragma unroll
    for (int o = 16; o; o >>= 1) sum += __shfl_down_sync(0xffffffffu, sum, o);
    if (!(t & 31)) sm[t >> 5] = sum;
    __syncthreads();
    if (t == 0) {
        float tt = 0.f;
#pragma unroll
        for (int i = 0; i < 8; i++) tt += sm[i];
        bc = 1.f / tt;
    }
    __syncthreads();
    float inv = bc;
    float4 a = make_float4(e.x * inv, e.y * inv, e.z * inv, e.w * inv);
    ((float4*)satt)[t] = a;
    __syncthreads();
    if (sc == 0) {
        ((float4*)g_attn)[b * 256 + t] = a;
        ((float4*)out_attn)[b * 256 + t] = a;
    }
    int s0 = sc * (SS / NSC);
    float4 acc = make_float4(0.f, 0.f, 0.f, 0.f);
    const float4* base = enc + (size_t)(b * SS + s0) * 256 + t;
#pragma unroll 8
    for (int ss = 0; ss < SS / NSC; ss++) {
        float  aa = satt[s0 + ss];
        float4 ee = base[(size_t)ss * 256];
        acc.x += aa * ee.x; acc.y += aa * ee.y; acc.z += aa * ee.z; acc.w += aa * ee.w;
    }
    ((float4*)g_ctxpart)[(sc * 32 + b) * 256 + t] = acc;
    __syncthreads();
    if (t == 0) {
        __threadfence();
        int old = atomicAdd(&g_ctr_ctx[b], 1);
        slast = (old == NSC - 1);
    }
    __syncthreads();
    if (!slast) return;
    __threadfence();
    float sv[4] = {0.f, 0.f, 0.f, 0.f};
#pragma unroll
    for (int scc = 0; scc < NSC; scc++) {
        float4 p = __ldcg(((const float4*)g_ctxpart) + (scc * 32 + b) * 256 + t);
        sv[0] += p.x; sv[1] += p.y; sv[2] += p.z; sv[3] += p.w;
    }
    int d = 4 * t;
    float ctx[4];
    float pp = 0.f;
#pragma unroll
    for (int i = 0; i < 4; i++) {
        int dd = d + i;
        float cx = (sv[i] - bn_m[dd]) * rsqrtf(bn_v[dd] + 1e-5f) * gam[dd] + bet[dd];
        ctx[i] = cx;
        g_temp_t[(DD + dd) * 32 + b] = cx;
        float dop = (dd < DD) ? h[b * DD + dd] : c[b * DD + dd - DD];
        pp += Wp[dd] * cx + Wp[D2 + dd] * dop;
    }
    ((float4*)out_ctx)[b * 256 + t] = make_float4(ctx[0], ctx[1], ctx[2], ctx[3]);
    if (t < 128) {
#pragma unroll
        for (int i = 0; i < 4; i++) {
            int dd = 4 * t + i;
            pp += Wp[2048 + dd] * dinp[b * DD + dd];
        }
    }
#pragma unroll
    for (int o = 16; o; o >>= 1) pp += __shfl_down_sync(0xffffffffu, pp, o);
    if (!(t & 31)) sm[t >> 5] = pp;
    __syncthreads();
    if (t == 0) {
        float tot = bp[0];
#pragma unroll
        for (int i = 0; i < 8; i++) tot += sm[i];
        g_pgen[b] = 1.f / (1.f + __expf(-tot));
    }
}

// ===========================================================================
// C: fused k6 (hidden GEMM, bids 0..47) + k8a (vocab logits, bids 48..431)
// ===========================================================================
#define XS6  68
#define WSTR 20
__global__ void __launch_bounds__(256, 2)
kC_hidden_logits(const float* __restrict__ Wv1, const float* __restrict__ bv1,
                 const float* __restrict__ Wv2) {
    __shared__ __align__(16) float cbuf[10880];
    __shared__ int slast;
    int t = threadIdx.x;
    int bid = blockIdx.x;

    if (bid < 48) {
        float* sW = cbuf;
        float* sX = cbuf + 128 * XS6;
        int tj = t & 63, tb = t >> 6;
        int jb = bid & 3, kb = bid >> 2;
        int j0 = jb * 128;
        unsigned long long acc2[2][8];
#pragma unroll
        for (int jr = 0; jr < 2; jr++)
#pragma unroll
            for (int bj = 0; bj < 8; bj++) acc2[jr][bj] = 0ull;
#pragma unroll
        for (int sub = 0; sub < 2; sub++) {
            int k0s = kb * 128 + sub * 64;
            __syncthreads();
#pragma unroll
            for (int li = 0; li < 8; li++) {
                int flat = li * 256 + t;
                int row = flat >> 4, kc = flat & 15;
                float4 f = *(const float4*)(Wv1 + (size_t)(j0 + row) * D3 + k0s + kc * 4);
                *(float4*)(sW + row * XS6 + kc * 4) = f;
            }
#pragma unroll
            for (int li = 0; li < 2; li++) {
                int flat = li * 256 + t;
                int kk = flat >> 3, bq = flat & 7;
                float4 f = ((const float4*)g_temp_t)[(size_t)(k0s + kk) * 8 + bq];
                sX[(bq * 4 + 0) * XS6 + kk] = f.x;
                sX[(bq * 4 + 1) * XS6 + kk] = f.y;
                sX[(bq * 4 + 2) * XS6 + kk] = f.z;
                sX[(bq * 4 + 3) * XS6 + kk] = f.w;
            }
            __syncthreads();
#pragma unroll
            for (int kq = 0; kq < 16; kq++) {
                ulonglong2 xv[8];
#pragma unroll
                for (int bj = 0; bj < 8; bj++)
                    xv[bj] = *(const ulonglong2*)(sX + (tb * 8 + bj) * XS6 + kq * 4);
#pragma unroll
                for (int jr = 0; jr < 2; jr++) {
                    ulonglong2 wv = *(const ulonglong2*)(sW + (jr * 64 + tj) * XS6 + kq * 4);
#pragma unroll
                    for (int bj = 0; bj < 8; bj++) {
                        asm("fma.rn.f32x2 %0, %1, %2, %0;"
                            : "+l"(acc2[jr][bj]) : "l"(wv.x), "l"(xv[bj].x));
                        asm("fma.rn.f32x2 %0, %1, %2, %0;"
                            : "+l"(acc2[jr][bj]) : "l"(wv.y), "l"(xv[bj].y));
                    }
                }
            }
        }
#pragma unroll
        for (int jr = 0; jr < 2; jr++)
#pragma unroll
            for (int bj = 0; bj < 8; bj++) {
                unsigned long long a = acc2[jr][bj];
                float v = __uint_as_float((unsigned)(a & 0xffffffffu)) +
                          __uint_as_float((unsigned)(a >> 32));
                g_hpart[((size_t)kb * 32 + tb * 8 + bj) * DD + j0 + jr * 64 + tj] = v;
            }
        __syncthreads();
        if (t == 0) {
            __threadfence();
            int old = atomicAdd(&g_ctr_h[jb], 1);
            slast = (old == KB6 - 1);
        }
        __syncthreads();
        if (!slast) return;
        __threadfence();
#pragma unroll
        for (int li = 0; li < 4; li++) {
            int flat = li * 256 + t;
            int b = flat >> 5, jq = flat & 31;
            float4 sum = *(const float4*)(bv1 + j0 + jq * 4);
#pragma unroll
            for (int p = 0; p < KB6; p++) {
                float4 v = __ldcg((const float4*)(g_hpart + ((size_t)p * 32 + b) * DD + j0 + jq * 4));
                sum.x += v.x; sum.y += v.y; sum.z += v.z; sum.w += v.w;
            }
            *(float4*)(g_hidden + (size_t)b * DD + j0 + jq * 4) = sum;
        }
        __threadfence();
        __syncthreads();
        if (t == 0) atomicAdd(&g_hready, 1);
        return;
    }

    // ---- k8a part ----
    float* Ws = cbuf;
    float* Hs = cbuf + 256 * WSTR;
    int idx = bid - 48;
    if (idx == 0 && t < BB) { g_sumtot[t] = 0.f; g_ctr_v[t] = 0; }
    int tv = t & 63, tb = t >> 6;
    int v0 = (idx % 192) * 256;
    int ks = idx / 192;
    int kbase = ks * 256;

    unsigned long long acc2[4][8];
#pragma unroll
    for (int j = 0; j < 4; j++)
#pragma unroll
        for (int bj = 0; bj < 8; bj++) acc2[j][bj] = 0ull;

    float4 wreg[4];
    float  hreg0, hreg1;
    {
        int k0 = kbase;
#pragma unroll
        for (int li = 0; li < 4; li++) {
            int flat = li * 256 + t;
            int v = flat >> 2, kq = flat & 3;
            int gv = v0 + v;
            wreg[li] = (gv < VV)
                ? *(const float4*)(Wv2 + (size_t)gv * DD + k0 + kq * 4)
                : make_float4(0.f, 0.f, 0.f, 0.f);
        }
#pragma unroll
        for (int li = 0; li < 4; li++) {
            int flat = li * 256 + t;
            int v = flat >> 2, kq = flat & 3;
            *(float4*)(Ws + v * WSTR + kq * 4) = wreg[li];
        }
    }
    if (t == 0) {
        while (*(volatile int*)&g_hready < JB6) __nanosleep(64);
    }
    __syncthreads();
    __threadfence();
    {
        int k0 = kbase;
        hreg0 = __ldcg(&g_hidden[((t)       >> 4) * DD + k0 + ((t)       & 15)]);
        hreg1 = __ldcg(&g_hidden[((t + 256) >> 4) * DD + k0 + ((t + 256) & 15)]);
        Hs[t] = hreg0;
        Hs[t + 256] = hreg1;
    }
    __syncthreads();

    for (int tile = 0; tile < 16; tile++) {
        if (tile < 15) {
            int k0 = kbase + (tile + 1) * 16;
#pragma unroll
            for (int li = 0; li < 4; li++) {
                int flat = li * 256 + t;
                int v = flat >> 2, kq = flat & 3;
                int gv = v0 + v;
                wreg[li] = (gv < VV)
                    ? *(const float4*)(Wv2 + (size_t)gv * DD + k0 + kq * 4)
                    : make_float4(0.f, 0.f, 0.f, 0.f);
            }
            hreg0 = g_hidden[((t)       >> 4) * DD + k0 + ((t)       & 15)];
            hreg1 = g_hidden[((t + 256) >> 4) * DD + k0 + ((t + 256) & 15)];
        }
#pragma unroll
        for (int kq = 0; kq < 4; kq++) {
            ulonglong2 h2[8];
#pragma unroll
            for (int bj = 0; bj < 8; bj++)
                h2[bj] = *(const ulonglong2*)(Hs + (tb * 8 + bj) * 16 + kq * 4);
#pragma unroll
            for (int j = 0; j < 4; j++) {
                ulonglong2 w2 = *(const ulonglong2*)(Ws + (tv + 64 * j) * WSTR + kq * 4);
#pragma unroll
                for (int bj = 0; bj < 8; bj++) {
                    asm("fma.rn.f32x2 %0, %1, %2, %0;"
                        : "+l"(acc2[j][bj]) : "l"(w2.x), "l"(h2[bj].x));
                    asm("fma.rn.f32x2 %0, %1, %2, %0;"
                        : "+l"(acc2[j][bj]) : "l"(w2.y), "l"(h2[bj].y));
                }
            }
        }
        if (tile < 15) {
            __syncthreads();
#pragma unroll
            for (int li = 0; li < 4; li++) {
                int flat = li * 256 + t;
                int v = flat >> 2, kq = flat & 3;
                *(float4*)(Ws + v * WSTR + kq * 4) = wreg[li];
            }
            Hs[t] = hreg0;
            Hs[t + 256] = hreg1;
            __syncthreads();
        }
    }
    float accf[4][8];
#pragma unroll
    for (int j = 0; j < 4; j++)
#pragma unroll
        for (int bj = 0; bj < 8; bj++) {
            unsigned long long a = acc2[j][bj];
            accf[j][bj] = __uint_as_float((unsigned)(a & 0xffffffffu)) +
                          __uint_as_float((unsigned)(a >> 32));
        }
#pragma unroll
    for (int p = 0; p < 2; p++) {
        __syncthreads();
        if ((tb >> 1) == p) {
#pragma unroll
            for (int j = 0; j < 4; j++)
#pragma unroll
                for (int bj = 0; bj < 8; bj++)
                    Ws[((tb & 1) * 8 + bj) * 256 + tv + 64 * j] = accf[j][bj];
        }
        __syncthreads();
#pragma unroll
        for (int i = 0; i < 4; i++) {
            int ii = i * 256 + t;
            int row = ii >> 6, col = ii & 63;
            *(float4*)(g_lpart + ((size_t)(ks * 32 + p * 16 + row) * VP + v0 + col * 4)) =
                *(const float4*)(Ws + row * 256 + col * 4);
        }
    }
}

// ===========================================================================
// D: exp (kept in regs) + per-b sum; per-block LOCAL scatter in smem; spin only
//    on scalar sum counter; single-pass combine + zero-fix. Zeroes kA counters.
// ===========================================================================
__global__ void kD_exp_final(const float* __restrict__ bv2, float* __restrict__ dout,
                             const int* __restrict__ src) {
    __shared__ float ssc[2048];
    __shared__ float sm[8];
    int b = blockIdx.x, cb = blockIdx.y, t = threadIdx.x;
    if (b == 0 && cb == 0) {
        if (t == 0) { g_ctr_dec1 = 0; g_hready = 0; }
        if (t < BB) { g_ctr_s[t] = 0; g_ctr_ctx[t] = 0; }
        if (t < JB6) g_ctr_h[t] = 0;
    }
    int base = cb * 2048;
    float pg = g_pgen[b];
    float ev[8];
    float sum = 0.f;
#pragma unroll
    for (int it = 0; it < 8; it++) {
        int v = base + it * 256 + t;
        float e = 0.f;
        if (v < VV) {
            float l = g_lpart[(size_t)b * VP + v] + g_lpart[(size_t)(32 + b) * VP + v] + bv2[v];
            e = __expf(l);
            sum += e;
        }
        ev[it] = e;
    }
#pragma unroll
    for (int o = 16; o; o >>= 1) sum += __shfl_down_sync(0xffffffffu, sum, o);
    if (!(t & 31)) sm[t >> 5] = sum;
    __syncthreads();
    if (t == 0) {
        float tot = 0.f;
#pragma unroll
        for (int i = 0; i < 8; i++) tot += sm[i];
        atomicAdd(&g_sumtot[b], tot);
        __threadfence();
        atomicAdd(&g_ctr_v[b], 1);
    }
    // local scatter into smem (no cross-block dependency)
#pragma unroll
    for (int i = 0; i < 8; i++) ssc[i * 256 + t] = 0.f;
    __syncthreads();
#pragma unroll
    for (int i = 0; i < 4; i++) {
        int si = i * 256 + t;
        int idx = src[b * SS + si];
        int off = idx - base;
        if ((unsigned)off < 2048u)
            atomicAdd(&ssc[off], g_attn[b * SS + si]);
    }
    __syncthreads();
    // wait for full softmax sum (scalar), then combine
    if (t == 0) {
        while (*(volatile int*)&g_ctr_v[b] < NCB) __nanosleep(32);
    }
    __syncthreads();
    __threadfence();
    float s  = __ldcg(&g_sumtot[b]);
    float sc = pg / s;
    float f  = 1.f - pg;
#pragma unroll
    for (int it = 0; it < 8; it++) {
        int v = base + it * 256 + t;
        if (v < VF) {
            float p = ev[it] * sc + f * ssc[it * 256 + t];
            if (p == 0.f) p = 1e-12f;
            dout[(size_t)b * VF + v] = p;
        }
    }
}

extern "C" void kernel_launch(void* const* d_in, const int* in_sizes, int n_in,
                              void* d_out, int out_size) {
    const float* dec_output = (const float*)d_in[0];
    const float* hh         = (const float*)d_in[1];
    const float* cc         = (const float*)d_in[2];
    const float* dinp       = (const float*)d_in[3];
    const float* enc        = (const float*)d_in[4];
    const float* enc1       = (const float*)d_in[5];
    const int*   src        = (const int*)  d_in[6];
    const float* W_dec      = (const float*)d_in[7];
    const float* b_dec      = (const float*)d_in[8];
    const float* w_attn     = (const float*)d_in[9];
    const float* W_v1       = (const float*)d_in[10];
    const float* b_v1       = (const float*)d_in[11];
    const float* W_v2       = (const float*)d_in[12];
    const float* b_v2       = (const float*)d_in[13];
    const float* W_p        = (const float*)d_in[14];
    const float* b_p        = (const float*)d_in[15];
    const float* gam        = (const float*)d_in[16];
    const float* bet        = (const float*)d_in[17];
    const float* bn_m       = (const float*)d_in[18];
    const float* bn_v       = (const float*)d_in[19];

    float* dout     = (float*)d_out;
    float* out_attn = dout + BB * VF;
    float* out_ctx  = out_attn + BB * SS;

    kA_all<<<4736, 256>>>(hh, cc, dec_output, W_dec, b_dec,
                          (const float4*)enc1, (const float4*)w_attn,
                          (const float4*)enc, src, out_attn,
                          bn_m, bn_v, gam, bet, W_p, b_p, dinp, out_ctx);
    kC_hidden_logits<<<432, 256>>>(W_v1, b_v1, W_v2);
    kD_exp_final  <<<dim3(32, NCB), 256>>>(b_v2, dout, src);
}

// round 10
// speedup vs baseline: 1.5284x; 1.0376x over previous
#include <cuda_runtime.h>

#define BB   32
#define SS   1024
#define DD   512
#define D2   1024
#define D3   1536
#define VV   49000
#define VP   49152
#define VF   50000
#define NCB  25
#define NSC  16
#define KB6  12
#define JB6  4

__device__ __align__(16) float g_temp_t [D3 * BB];
__device__ __align__(16) float g_dpart  [4 * BB * D2];
__device__ __align__(16) float g_dec1   [BB * D2];
__device__ __align__(16) float g_scores [BB * SS];
__device__ __align__(16) float g_attn   [BB * SS];
__device__ __align__(16) float g_ctxpart[NSC * BB * D2];
__device__ __align__(16) float g_hpart  [KB6 * BB * DD];
__device__ __align__(16) float g_hidden [BB * DD];
__device__            float g_pgen  [BB];
__device__ __align__(16) float g_lpart [2 * BB * VP];
__device__            float g_sumtot[BB];
__device__            int   g_ctr_d  [128];
__device__            int   g_ctr_dec1;
__device__            int   g_ctr_s  [BB];
__device__            int   g_ctr_ctx[BB];
__device__            int   g_ctr_v  [BB];
__device__            int   g_ctr_h  [JB6];
__device__            int   g_hready;

__device__ __forceinline__ float fast_tanh(float x) {
    float y;
    asm("tanh.approx.f32 %0, %1;" : "=f"(y) : "f"(x));
    return y;
}

// ===========================================================================
// A: dec1 split-K GEMV (bids 0..511) + scores (512..4607) + softmax/ctx (4608..5119)
// ===========================================================================
__global__ void __launch_bounds__(256, 5)
kA_all(const float* __restrict__ h, const float* __restrict__ c,
       const float* __restrict__ dec_output,
       const float* __restrict__ W, const float* __restrict__ bias,
       const float4* __restrict__ enc1, const float4* __restrict__ wattn,
       const float4* __restrict__ enc, const int* __restrict__ src,
       float* __restrict__ out_attn,
       const float* __restrict__ bn_m, const float* __restrict__ bn_v,
       const float* __restrict__ gam,  const float* __restrict__ bet,
       const float* __restrict__ Wp,   const float* __restrict__ bp,
       const float* __restrict__ dinp, float* __restrict__ out_ctx) {
    __shared__ __align__(16) float abuf[5152];
    __shared__ float sm[8];
    __shared__ float bc;
    __shared__ int slast;
    int t = threadIdx.x;
    int bid = blockIdx.x;

    if (bid < 512) {
        // ---- dec1 split-K: jb = bid>>2 (8 j each), ks = bid&3 (256 k each) ----
        int jb = bid >> 2, ks = bid & 3;
        int j0 = jb * 8;
        float* sdec = abuf;            // [32][129]
        float* sW   = abuf + 4128;     // [8][128]
        int jj = t >> 5, b = t & 31;
        if (bid < 128 && t < 128) {
            int i = bid * 128 + t;
            int k = i >> 5, bb = i & 31;
            g_temp_t[i] = dec_output[bb * DD + k];
        }
        float a0 = 0.f, a1 = 0.f, a2 = 0.f, a3 = 0.f;
#pragma unroll
        for (int ch = 0; ch < 2; ch++) {
            int k0 = ks * 256 + ch * 128;
            __syncthreads();
#pragma unroll
            for (int m = 0; m < 16; m++) {
                int e = m * 256 + t;
                int bb = e >> 7, kk = e & 127;
                int kg = k0 + kk;
                sdec[bb * 129 + kk] = (kg < DD) ? h[bb * DD + kg] : c[bb * DD + kg - DD];
            }
#pragma unroll
            for (int m = 0; m < 4; m++) {
                int e = m * 256 + t;
                int jx = e >> 7, kk = e & 127;
                sW[jx * 128 + kk] = W[(j0 + jx) * D2 + k0 + kk];
            }
            __syncthreads();
#pragma unroll
            for (int kk = 0; kk < 128; kk += 4) {
                a0 += sW[jj * 128 + kk + 0] * sdec[b * 129 + kk + 0];
                a1 += sW[jj * 128 + kk + 1] * sdec[b * 129 + kk + 1];
                a2 += sW[jj * 128 + kk + 2] * sdec[b * 129 + kk + 2];
                a3 += sW[jj * 128 + kk + 3] * sdec[b * 129 + kk + 3];
            }
        }
        g_dpart[(ks * 32 + b) * D2 + j0 + jj] = (a0 + a1) + (a2 + a3);
        __syncthreads();
        if (t == 0) {
            __threadfence();
            int old = atomicAdd(&g_ctr_d[jb], 1);
            slast = (old == 3);
        }
        __syncthreads();
        if (!slast) return;
        __threadfence();
        float tot = bias[j0 + jj];
#pragma unroll
        for (int ks2 = 0; ks2 < 4; ks2++)
            tot += __ldcg(&g_dpart[(ks2 * 32 + b) * D2 + j0 + jj]);
        g_dec1[b * D2 + j0 + jj] = tot;
        __threadfence();
        __syncthreads();
        if (t == 0) atomicAdd(&g_ctr_dec1, 1);
        return;
    }

    if (bid < 4608) {
        // ---- scores (streamed loads, no prefetch buffer) ----
        float4* sd1 = (float4*)abuf;          // [256]
        float4* swa = ((float4*)abuf) + 256;  // [256]
        int row0 = (bid - 512) * 8;
        int b = row0 >> 10;
        swa[t] = wattn[t];
        if (t == 0) {
            while (*(volatile int*)&g_ctr_dec1 < 128) __nanosleep(64);
        }
        __syncthreads();
        __threadfence();
        sd1[t] = __ldcg(((const float4*)g_dec1) + b * 256 + t);
        __syncthreads();
        int lane = t & 31, w = t >> 5;
        int row = row0 + w;
        const float4* erow = enc1 + (size_t)row * 256;
        float acc = 0.f;
#pragma unroll
        for (int i = 0; i < 8; i++) {
            int cidx = i * 32 + lane;
            float4 ee = erow[cidx];
            float4 dd = sd1[cidx];
            float4 wa = swa[cidx];
            acc += fast_tanh(ee.x + dd.x) * wa.x;
            acc += fast_tanh(ee.y + dd.y) * wa.y;
            acc += fast_tanh(ee.z + dd.z) * wa.z;
            acc += fast_tanh(ee.w + dd.w) * wa.w;
        }
#pragma unroll
        for (int o = 16; o; o >>= 1) acc += __shfl_down_sync(0xffffffffu, acc, o);
        if (!lane) g_scores[row] = acc;
        __threadfence();
        __syncthreads();
        if (t == 0) atomicAdd(&g_ctr_s[b], 1);
        return;
    }

    // ---- softmax + context partial + last-block tail ----
    int idx = bid - 4608;
    int b = idx & 31, sc = idx >> 5;
    float* satt = abuf;   // [1024]
    if (t == 0) {
        while (*(volatile int*)&g_ctr_s[b] < 128) __nanosleep(64);
    }
    __syncthreads();
    __threadfence();
    float4 s = __ldcg(((const float4*)g_scores) + b * 256 + t);
    float m = fmaxf(fmaxf(s.x, s.y), fmaxf(s.z, s.w));
#pragma unroll
    for (int o = 16; o; o >>= 1) m = fmaxf(m, __shfl_down_sync(0xffffffffu, m, o));
    if (!(t & 31)) sm[t >> 5] = m;
    __syncthreads();
    if (t == 0) {
        float mm = sm[0];
#pragma unroll
        for (int i = 1; i < 8; i++) mm = fmaxf(mm, sm[i]);
        bc = mm;
    }
    __syncthreads();
    float mx = bc;
    __syncthreads();
    int4 id = ((const int4*)src)[b * 256 + t];
    float4 e;
    e.x = (id.x != 0) ? __expf(s.x - mx) : 0.f;
    e.y = (id.y != 0) ? __expf(s.y - mx) : 0.f;
    e.z = (id.z != 0) ? __expf(s.z - mx) : 0.f;
    e.w = (id.w != 0) ? __expf(s.w - mx) : 0.f;
    float sum = e.x + e.y + e.z + e.w;
#pragma unroll
    for (int o = 16; o; o >>= 1) sum += __shfl_down_sync(0xffffffffu, sum, o);
    if (!(t & 31)) sm[t >> 5] = sum;
    __syncthreads();
    if (t == 0) {
        float tt = 0.f;
#pragma unroll
        for (int i = 0; i < 8; i++) tt += sm[i];
        bc = 1.f / tt;
    }
    __syncthreads();
    float inv = bc;
    float4 a = make_float4(e.x * inv, e.y * inv, e.z * inv, e.w * inv);
    ((float4*)satt)[t] = a;
    __syncthreads();
    if (sc == 0) {
        ((float4*)g_attn)[b * 256 + t] = a;
        ((float4*)out_attn)[b * 256 + t] = a;
    }
    int s0 = sc * (SS / NSC);
    float4 acc = make_float4(0.f, 0.f, 0.f, 0.f);
    const float4* base = enc + (size_t)(b * SS + s0) * 256 + t;
#pragma unroll 8
    for (int ss = 0; ss < SS / NSC; ss++) {
        float  aa = satt[s0 + ss];
        float4 ee = base[(size_t)ss * 256];
        acc.x += aa * ee.x; acc.y += aa * ee.y; acc.z += aa * ee.z; acc.w += aa * ee.w;
    }
    ((float4*)g_ctxpart)[(sc * 32 + b) * 256 + t] = acc;
    __syncthreads();
    if (t == 0) {
        __threadfence();
        int old = atomicAdd(&g_ctr_ctx[b], 1);
        slast = (old == NSC - 1);
    }
    __syncthreads();
    if (!slast) return;
    __threadfence();
    float sv[4] = {0.f, 0.f, 0.f, 0.f};
#pragma unroll
    for (int scc = 0; scc < NSC; scc++) {
        float4 p = __ldcg(((const float4*)g_ctxpart) + (scc * 32 + b) * 256 + t);
        sv[0] += p.x; sv[1] += p.y; sv[2] += p.z; sv[3] += p.w;
    }
    int d = 4 * t;
    float ctx[4];
    float pp = 0.f;
#pragma unroll
    for (int i = 0; i < 4; i++) {
        int dd = d + i;
        float cx = (sv[i] - bn_m[dd]) * rsqrtf(bn_v[dd] + 1e-5f) * gam[dd] + bet[dd];
        ctx[i] = cx;
        g_temp_t[(DD + dd) * 32 + b] = cx;
        float dop = (dd < DD) ? h[b * DD + dd] : c[b * DD + dd - DD];
        pp += Wp[dd] * cx + Wp[D2 + dd] * dop;
    }
    ((float4*)out_ctx)[b * 256 + t] = make_float4(ctx[0], ctx[1], ctx[2], ctx[3]);
    if (t < 128) {
#pragma unroll
        for (int i = 0; i < 4; i++) {
            int dd = 4 * t + i;
            pp += Wp[2048 + dd] * dinp[b * DD + dd];
        }
    }
#pragma unroll
    for (int o = 16; o; o >>= 1) pp += __shfl_down_sync(0xffffffffu, pp, o);
    if (!(t & 31)) sm[t >> 5] = pp;
    __syncthreads();
    if (t == 0) {
        float tot = bp[0];
#pragma unroll
        for (int i = 0; i < 8; i++) tot += sm[i];
        g_pgen[b] = 1.f / (1.f + __expf(-tot));
    }
}

// ===========================================================================
// C: fused k6 (hidden GEMM, bids 0..47) + k8a (vocab logits, bids 48..431)
// ===========================================================================
#define XS6  68
#define WSTR 20
__global__ void __launch_bounds__(256, 2)
kC_hidden_logits(const float* __restrict__ Wv1, const float* __restrict__ bv1,
                 const float* __restrict__ Wv2) {
    __shared__ __align__(16) float cbuf[10880];
    __shared__ int slast;
    int t = threadIdx.x;
    int bid = blockIdx.x;

    if (bid < 48) {
        float* sW = cbuf;
        float* sX = cbuf + 128 * XS6;
        int tj = t & 63, tb = t >> 6;
        int jb = bid & 3, kb = bid >> 2;
        int j0 = jb * 128;
        unsigned long long acc2[2][8];
#pragma unroll
        for (int jr = 0; jr < 2; jr++)
#pragma unroll
            for (int bj = 0; bj < 8; bj++) acc2[jr][bj] = 0ull;
#pragma unroll
        for (int sub = 0; sub < 2; sub++) {
            int k0s = kb * 128 + sub * 64;
            __syncthreads();
#pragma unroll
            for (int li = 0; li < 8; li++) {
                int flat = li * 256 + t;
                int row = flat >> 4, kc = flat & 15;
                float4 f = *(const float4*)(Wv1 + (size_t)(j0 + row) * D3 + k0s + kc * 4);
                *(float4*)(sW + row * XS6 + kc * 4) = f;
            }
#pragma unroll
            for (int li = 0; li < 2; li++) {
                int flat = li * 256 + t;
                int kk = flat >> 3, bq = flat & 7;
                float4 f = ((const float4*)g_temp_t)[(size_t)(k0s + kk) * 8 + bq];
                sX[(bq * 4 + 0) * XS6 + kk] = f.x;
                sX[(bq * 4 + 1) * XS6 + kk] = f.y;
                sX[(bq * 4 + 2) * XS6 + kk] = f.z;
                sX[(bq * 4 + 3) * XS6 + kk] = f.w;
            }
            __syncthreads();
#pragma unroll
            for (int kq = 0; kq < 16; kq++) {
                ulonglong2 xv[8];
#pragma unroll
                for (int bj = 0; bj < 8; bj++)
                    xv[bj] = *(const ulonglong2*)(sX + (tb * 8 + bj) * XS6 + kq * 4);
#pragma unroll
                for (int jr = 0; jr < 2; jr++) {
                    ulonglong2 wv = *(const ulonglong2*)(sW + (jr * 64 + tj) * XS6 + kq * 4);
#pragma unroll
                    for (int bj = 0; bj < 8; bj++) {
                        asm("fma.rn.f32x2 %0, %1, %2, %0;"
                            : "+l"(acc2[jr][bj]) : "l"(wv.x), "l"(xv[bj].x));
                        asm("fma.rn.f32x2 %0, %1, %2, %0;"
                            : "+l"(acc2[jr][bj]) : "l"(wv.y), "l"(xv[bj].y));
                    }
                }
            }
        }
#pragma unroll
        for (int jr = 0; jr < 2; jr++)
#pragma unroll
            for (int bj = 0; bj < 8; bj++) {
                unsigned long long a = acc2[jr][bj];
                float v = __uint_as_float((unsigned)(a & 0xffffffffu)) +
                          __uint_as_float((unsigned)(a >> 32));
                g_hpart[((size_t)kb * 32 + tb * 8 + bj) * DD + j0 + jr * 64 + tj] = v;
            }
        __syncthreads();
        if (t == 0) {
            __threadfence();
            int old = atomicAdd(&g_ctr_h[jb], 1);
            slast = (old == KB6 - 1);
        }
        __syncthreads();
        if (!slast) return;
        __threadfence();
#pragma unroll
        for (int li = 0; li < 4; li++) {
            int flat = li * 256 + t;
            int b = flat >> 5, jq = flat & 31;
            float4 sum = *(const float4*)(bv1 + j0 + jq * 4);
#pragma unroll
            for (int p = 0; p < KB6; p++) {
                float4 v = __ldcg((const float4*)(g_hpart + ((size_t)p * 32 + b) * DD + j0 + jq * 4));
                sum.x += v.x; sum.y += v.y; sum.z += v.z; sum.w += v.w;
            }
            *(float4*)(g_hidden + (size_t)b * DD + j0 + jq * 4) = sum;
        }
        __threadfence();
        __syncthreads();
        if (t == 0) atomicAdd(&g_hready, 1);
        return;
    }

    // ---- k8a part ----
    float* Ws = cbuf;
    float* Hs = cbuf + 256 * WSTR;
    int idx = bid - 48;
    if (idx == 0 && t < BB) { g_sumtot[t] = 0.f; g_ctr_v[t] = 0; }
    int tv = t & 63, tb = t >> 6;
    int v0 = (idx % 192) * 256;
    int ks = idx / 192;
    int kbase = ks * 256;

    unsigned long long acc2[4][8];
#pragma unroll
    for (int j = 0; j < 4; j++)
#pragma unroll
        for (int bj = 0; bj < 8; bj++) acc2[j][bj] = 0ull;

    float4 wreg[4];
    float  hreg0, hreg1;
    {
        int k0 = kbase;
#pragma unroll
        for (int li = 0; li < 4; li++) {
            int flat = li * 256 + t;
            int v = flat >> 2, kq = flat & 3;
            int gv = v0 + v;
            wreg[li] = (gv < VV)
                ? *(const float4*)(Wv2 + (size_t)gv * DD + k0 + kq * 4)
                : make_float4(0.f, 0.f, 0.f, 0.f);
        }
#pragma unroll
        for (int li = 0; li < 4; li++) {
            int flat = li * 256 + t;
            int v = flat >> 2, kq = flat & 3;
            *(float4*)(Ws + v * WSTR + kq * 4) = wreg[li];
        }
    }
    if (t == 0) {
        while (*(volatile int*)&g_hready < JB6) __nanosleep(64);
    }
    __syncthreads();
    __threadfence();
    {
        int k0 = kbase;
        hreg0 = __ldcg(&g_hidden[((t)       >> 4) * DD + k0 + ((t)       & 15)]);
        hreg1 = __ldcg(&g_hidden[((t + 256) >> 4) * DD + k0 + ((t + 256) & 15)]);
        Hs[t] = hreg0;
        Hs[t + 256] = hreg1;
    }
    __syncthreads();

    for (int tile = 0; tile < 16; tile++) {
        if (tile < 15) {
            int k0 = kbase + (tile + 1) * 16;
#pragma unroll
            for (int li = 0; li < 4; li++) {
                int flat = li * 256 + t;
                int v = flat >> 2, kq = flat & 3;
                int gv = v0 + v;
                wreg[li] = (gv < VV)
                    ? *(const float4*)(Wv2 + (size_t)gv * DD + k0 + kq * 4)
                    : make_float4(0.f, 0.f, 0.f, 0.f);
            }
            hreg0 = g_hidden[((t)       >> 4) * DD + k0 + ((t)       & 15)];
            hreg1 = g_hidden[((t + 256) >> 4) * DD + k0 + ((t + 256) & 15)];
        }
#pragma unroll
        for (int kq = 0; kq < 4; kq++) {
            ulonglong2 h2[8];
#pragma unroll
            for (int bj = 0; bj < 8; bj++)
                h2[bj] = *(const ulonglong2*)(Hs + (tb * 8 + bj) * 16 + kq * 4);
#pragma unroll
            for (int j = 0; j < 4; j++) {
                ulonglong2 w2 = *(const ulonglong2*)(Ws + (tv + 64 * j) * WSTR + kq * 4);
#pragma unroll
                for (int bj = 0; bj < 8; bj++) {
                    asm("fma.rn.f32x2 %0, %1, %2, %0;"
                        : "+l"(acc2[j][bj]) : "l"(w2.x), "l"(h2[bj].x));
                    asm("fma.rn.f32x2 %0, %1, %2, %0;"
                        : "+l"(acc2[j][bj]) : "l"(w2.y), "l"(h2[bj].y));
                }
            }
        }
        if (tile < 15) {
            __syncthreads();
#pragma unroll
            for (int li = 0; li < 4; li++) {
                int flat = li * 256 + t;
                int v = flat >> 2, kq = flat & 3;
                *(float4*)(Ws + v * WSTR + kq * 4) = wreg[li];
            }
            Hs[t] = hreg0;
            Hs[t + 256] = hreg1;
            __syncthreads();
        }
    }
    float accf[4][8];
#pragma unroll
    for (int j = 0; j < 4; j++)
#pragma unroll
        for (int bj = 0; bj < 8; bj++) {
            unsigned long long a = acc2[j][bj];
            accf[j][bj] = __uint_as_float((unsigned)(a & 0xffffffffu)) +
                          __uint_as_float((unsigned)(a >> 32));
        }
#pragma unroll
    for (int p = 0; p < 2; p++) {
        __syncthreads();
        if ((tb >> 1) == p) {
#pragma unroll
            for (int j = 0; j < 4; j++)
#pragma unroll
                for (int bj = 0; bj < 8; bj++)
                    Ws[((tb & 1) * 8 + bj) * 256 + tv + 64 * j] = accf[j][bj];
        }
        __syncthreads();
#pragma unroll
        for (int i = 0; i < 4; i++) {
            int ii = i * 256 + t;
            int row = ii >> 6, col = ii & 63;
            *(float4*)(g_lpart + ((size_t)(ks * 32 + p * 16 + row) * VP + v0 + col * 4)) =
                *(const float4*)(Ws + row * 256 + col * 4);
        }
    }
}

// ===========================================================================
// D: exp (regs) + per-b sum; local smem scatter; spin on sum counter only;
//    single-pass combine + zero-fix. Zeroes kA counters for next replay.
// ===========================================================================
__global__ void kD_exp_final(const float* __restrict__ bv2, float* __restrict__ dout,
                             const int* __restrict__ src) {
    __shared__ float ssc[2048];
    __shared__ float sm[8];
    int b = blockIdx.x, cb = blockIdx.y, t = threadIdx.x;
    if (b == 0 && cb == 0) {
        if (t == 0) { g_ctr_dec1 = 0; g_hready = 0; }
        if (t < BB) { g_ctr_s[t] = 0; g_ctr_ctx[t] = 0; }
        if (t < 128) g_ctr_d[t] = 0;
        if (t < JB6) g_ctr_h[t] = 0;
    }
    int base = cb * 2048;
    float pg = g_pgen[b];
    float ev[8];
    float sum = 0.f;
#pragma unroll
    for (int it = 0; it < 8; it++) {
        int v = base + it * 256 + t;
        float e = 0.f;
        if (v < VV) {
            float l = g_lpart[(size_t)b * VP + v] + g_lpart[(size_t)(32 + b) * VP + v] + bv2[v];
            e = __expf(l);
            sum += e;
        }
        ev[it] = e;
    }
#pragma unroll
    for (int o = 16; o; o >>= 1) sum += __shfl_down_sync(0xffffffffu, sum, o);
    if (!(t & 31)) sm[t >> 5] = sum;
    __syncthreads();
    if (t == 0) {
        float tot = 0.f;
#pragma unroll
        for (int i = 0; i < 8; i++) tot += sm[i];
        atomicAdd(&g_sumtot[b], tot);
        __threadfence();
        atomicAdd(&g_ctr_v[b], 1);
    }
#pragma unroll
    for (int i = 0; i < 8; i++) ssc[i * 256 + t] = 0.f;
    __syncthreads();
#pragma unroll
    for (int i = 0; i < 4; i++) {
        int si = i * 256 + t;
        int idx = src[b * SS + si];
        int off = idx - base;
        if ((unsigned)off < 2048u)
            atomicAdd(&ssc[off], g_attn[b * SS + si]);
    }
    __syncthreads();
    if (t == 0) {
        while (*(volatile int*)&g_ctr_v[b] < NCB) __nanosleep(32);
    }
    __syncthreads();
    __threadfence();
    float s  = __ldcg(&g_sumtot[b]);
    float sc = pg / s;
    float f  = 1.f - pg;
#pragma unroll
    for (int it = 0; it < 8; it++) {
        int v = base + it * 256 + t;
        if (v < VF) {
            float p = ev[it] * sc + f * ssc[it * 256 + t];
            if (p == 0.f) p = 1e-12f;
            dout[(size_t)b * VF + v] = p;
        }
    }
}

extern "C" void kernel_launch(void* const* d_in, const int* in_sizes, int n_in,
                              void* d_out, int out_size) {
    const float* dec_output = (const float*)d_in[0];
    const float* hh         = (const float*)d_in[1];
    const float* cc         = (const float*)d_in[2];
    const float* dinp       = (const float*)d_in[3];
    const float* enc        = (const float*)d_in[4];
    const float* enc1       = (const float*)d_in[5];
    const int*   src        = (const int*)  d_in[6];
    const float* W_dec      = (const float*)d_in[7];
    const float* b_dec      = (const float*)d_in[8];
    const float* w_attn     = (const float*)d_in[9];
    const float* W_v1       = (const float*)d_in[10];
    const float* b_v1       = (const float*)d_in[11];
    const float* W_v2       = (const float*)d_in[12];
    const float* b_v2       = (const float*)d_in[13];
    const float* W_p        = (const float*)d_in[14];
    const float* b_p        = (const float*)d_in[15];
    const float* gam        = (const float*)d_in[16];
    const float* bet        = (const float*)d_in[17];
    const float* bn_m       = (const float*)d_in[18];
    const float* bn_v       = (const float*)d_in[19];

    float* dout     = (float*)d_out;
    float* out_attn = dout + BB * VF;
    float* out_ctx  = out_attn + BB * SS;

    kA_all<<<5120, 256>>>(hh, cc, dec_output, W_dec, b_dec,
                          (const float4*)enc1, (const float4*)w_attn,
                          (const float4*)enc, src, out_attn,
                          bn_m, bn_v, gam, bet, W_p, b_p, dinp, out_ctx);
    kC_hidden_logits<<<432, 256>>>(W_v1, b_v1, W_v2);
    kD_exp_final  <<<dim3(32, NCB), 256>>>(b_v2, dout, src);
}